// round 3
// baseline (speedup 1.0000x reference)
#include <cuda_runtime.h>
#include <math.h>

#define B_  2
#define N_  2048
#define C_  1024
#define H_  16
#define HD_ 64

// Scratch (allocation-free: device globals). 4 x 16MB = 64MB.
__device__ float g_Q[B_*H_*N_*HD_];
__device__ float g_K[B_*H_*N_*HD_];
__device__ float g_V[B_*H_*N_*HD_];
__device__ float g_O[B_*N_*C_];

// ---------------------------------------------------------------------------
// Tiled SGEMM: C[m,d] = sum_k A[m,k] * W[d,k]  (both row-major, K-contig)
// BM=BN=128, BK=16, 256 threads, 8x8 micro-tile per thread.
// MODE 0: A = x (param), epilogue scatters into g_Q/g_K/g_V.
// MODE 1: A = g_O,       epilogue adds bias, writes outp[m*C_+d].
// ---------------------------------------------------------------------------
template<int MODE>
__global__ __launch_bounds__(256)
void gemm128(const float* __restrict__ Ain, const float* __restrict__ W,
             const float* __restrict__ bias, float* __restrict__ outp)
{
    const float* A = (MODE == 0) ? Ain : g_O;
    const int K = C_;

    __shared__ float As[16][128];
    __shared__ float Bs[16][128];

    int tid = threadIdx.x;
    int m0 = blockIdx.y * 128;
    int n0 = blockIdx.x * 128;
    int ty = tid / 16;        // 0..15 -> rows ty*8..ty*8+7
    int tx = tid % 16;        // 0..15 -> cols tx*8..tx*8+7

    // Load assignment: each thread loads 8 floats (2 float4) of A and W.
    int lr = tid >> 1;            // row within 128-tile
    int lc = (tid & 1) * 8;       // 0 or 8 within 16-wide k slab
    const float* aptr = A + (size_t)(m0 + lr) * K + lc;
    const float* bptr = W + (size_t)(n0 + lr) * K + lc;

    float acc[8][8];
    #pragma unroll
    for (int i = 0; i < 8; i++)
        #pragma unroll
        for (int j = 0; j < 8; j++) acc[i][j] = 0.f;

    for (int kt = 0; kt < K; kt += 16) {
        float4 a0 = *(const float4*)(aptr + kt);
        float4 a1 = *(const float4*)(aptr + kt + 4);
        float4 b0 = *(const float4*)(bptr + kt);
        float4 b1 = *(const float4*)(bptr + kt + 4);
        __syncthreads();
        As[lc+0][lr] = a0.x; As[lc+1][lr] = a0.y; As[lc+2][lr] = a0.z; As[lc+3][lr] = a0.w;
        As[lc+4][lr] = a1.x; As[lc+5][lr] = a1.y; As[lc+6][lr] = a1.z; As[lc+7][lr] = a1.w;
        Bs[lc+0][lr] = b0.x; Bs[lc+1][lr] = b0.y; Bs[lc+2][lr] = b0.z; Bs[lc+3][lr] = b0.w;
        Bs[lc+4][lr] = b1.x; Bs[lc+5][lr] = b1.y; Bs[lc+6][lr] = b1.z; Bs[lc+7][lr] = b1.w;
        __syncthreads();

        #pragma unroll
        for (int kk = 0; kk < 16; kk++) {
            float4 af0 = *(const float4*)&As[kk][ty*8];
            float4 af1 = *(const float4*)&As[kk][ty*8+4];
            float4 bf0 = *(const float4*)&Bs[kk][tx*8];
            float4 bf1 = *(const float4*)&Bs[kk][tx*8+4];
            float a[8] = {af0.x, af0.y, af0.z, af0.w, af1.x, af1.y, af1.z, af1.w};
            float bfr[8] = {bf0.x, bf0.y, bf0.z, bf0.w, bf1.x, bf1.y, bf1.z, bf1.w};
            #pragma unroll
            for (int i = 0; i < 8; i++)
                #pragma unroll
                for (int j = 0; j < 8; j++)
                    acc[i][j] += a[i] * bfr[j];
        }
    }

    if (MODE == 0) {
        #pragma unroll
        for (int i = 0; i < 8; i++) {
            int m = m0 + ty*8 + i;
            int b = m >> 11;          // / N_
            int n = m & (N_ - 1);
            #pragma unroll
            for (int j = 0; j < 8; j++) {
                int d = n0 + tx*8 + j;
                int which = d >> 10;          // 0=q,1=k,2=v
                int h = (d >> 6) & (H_ - 1);
                int e = d & (HD_ - 1);
                float* dst = (which == 0) ? g_Q : (which == 1) ? g_K : g_V;
                dst[((size_t)(b*H_ + h) * N_ + n) * HD_ + e] = acc[i][j];
            }
        }
    } else {
        #pragma unroll
        for (int i = 0; i < 8; i++) {
            int m = m0 + ty*8 + i;
            #pragma unroll
            for (int j = 0; j < 8; j++) {
                int d = n0 + tx*8 + j;
                outp[(size_t)m * C_ + d] = acc[i][j] + bias[d];
            }
        }
    }
}

// ---------------------------------------------------------------------------
// Fused per-head RMSNorm + RoPE for Q and K. One warp per (b,h,n) row.
// Lane l owns elements (2l, 2l+1) -> the rotate_half pair lives in one lane.
// ---------------------------------------------------------------------------
__global__ __launch_bounds__(256)
void rmsrope(const float* __restrict__ fc, const float* __restrict__ fs,
             const float* __restrict__ qg, const float* __restrict__ kg)
{
    int warp = threadIdx.x >> 5;
    int lane = threadIdx.x & 31;
    int row = blockIdx.x * 8 + warp;        // 0 .. B*H*N-1 in (b,h,n) order
    int b = row >> 15;                      // / (H_*N_)
    int n = row & (N_ - 1);

    size_t base = (size_t)row * HD_;
    size_t fb = ((size_t)(b * N_) + n) * HD_ + 2*lane;

    float2 fcv = *(const float2*)&fc[fb];
    float2 fsv = *(const float2*)&fs[fb];
    float2 qgv = *(const float2*)&qg[2*lane];
    float2 kgv = *(const float2*)&kg[2*lane];

    // Q
    {
        float2 q = *(const float2*)&g_Q[base + 2*lane];
        float ss = q.x*q.x + q.y*q.y;
        #pragma unroll
        for (int o = 16; o; o >>= 1) ss += __shfl_xor_sync(~0u, ss, o);
        float inv = 8.f / fmaxf(sqrtf(ss), 1e-12f);   // sqrt(HD)=8
        float nx = q.x * inv * qgv.x;
        float ny = q.y * inv * qgv.y;
        float2 o;
        o.x = nx * fcv.x - ny * fsv.x;
        o.y = ny * fcv.y + nx * fsv.y;
        *(float2*)&g_Q[base + 2*lane] = o;
    }
    // K
    {
        float2 k = *(const float2*)&g_K[base + 2*lane];
        float ss = k.x*k.x + k.y*k.y;
        #pragma unroll
        for (int o = 16; o; o >>= 1) ss += __shfl_xor_sync(~0u, ss, o);
        float inv = 8.f / fmaxf(sqrtf(ss), 1e-12f);
        float nx = k.x * inv * kgv.x;
        float ny = k.y * inv * kgv.y;
        float2 o;
        o.x = nx * fcv.x - ny * fsv.x;
        o.y = ny * fcv.y + nx * fsv.y;
        *(float2*)&g_K[base + 2*lane] = o;
    }
}

// ---------------------------------------------------------------------------
// Flash-style attention. Block = 64 q-rows of one (b,h). 32-key tiles.
// Online softmax with running max/sum; register O-accumulator 4x4/thread.
// Writes O directly in (B, N, H*hd) layout for the projection GEMM.
// ---------------------------------------------------------------------------
__global__ __launch_bounds__(256)
void attn_kernel(const float* __restrict__ mask)
{
    int q0 = blockIdx.x * 64;
    int h  = blockIdx.y;
    int b  = blockIdx.z;

    __shared__ float Qs[64][64];
    __shared__ float Ks[32][66];   // pad 66: conflict-free float2 reads
    __shared__ float Vs[32][64];
    __shared__ float Ss[64][33];
    __shared__ float rowm[64], rowl[64], rcorr[64];

    int tid = threadIdx.x;
    int ty = tid / 16, tx = tid % 16;
    int lane = tid & 31, warp = tid >> 5;
    int ty4 = ty * 4;

    size_t hb = (size_t)(b * H_ + h) * N_ * HD_;

    #pragma unroll
    for (int s = 0; s < 16; s++) {
        int idx = tid + s * 256;
        int r = idx >> 6, e = idx & 63;
        Qs[r][e] = g_Q[hb + (size_t)(q0 + r) * HD_ + e];
    }
    if (tid < 64) { rowm[tid] = -3.0e38f; rowl[tid] = 0.f; }

    float acc[4][4];
    #pragma unroll
    for (int i = 0; i < 4; i++)
        #pragma unroll
        for (int c = 0; c < 4; c++) acc[i][c] = 0.f;

    __syncthreads();

    for (int kt0 = 0; kt0 < N_; kt0 += 32) {
        // load K,V tiles (coalesced)
        #pragma unroll
        for (int s = 0; s < 8; s++) {
            int idx = tid + s * 256;
            int r = idx >> 6, e = idx & 63;
            size_t g = hb + (size_t)(kt0 + r) * HD_ + e;
            Ks[r][e] = g_K[g];
            Vs[r][e] = g_V[g];
        }
        __syncthreads();

        // S = (Q * scale) . K^T   (64 x 32 tile; thread: 4 rows x 2 cols)
        float sacc[4][2] = {{0.f,0.f},{0.f,0.f},{0.f,0.f},{0.f,0.f}};
        #pragma unroll 8
        for (int e = 0; e < 64; e += 2) {
            float2 a0 = *(const float2*)&Qs[ty4+0][e];
            float2 a1 = *(const float2*)&Qs[ty4+1][e];
            float2 a2 = *(const float2*)&Qs[ty4+2][e];
            float2 a3 = *(const float2*)&Qs[ty4+3][e];
            float2 b0 = *(const float2*)&Ks[tx*2+0][e];
            float2 b1 = *(const float2*)&Ks[tx*2+1][e];
            sacc[0][0] += a0.x*b0.x + a0.y*b0.y;
            sacc[0][1] += a0.x*b1.x + a0.y*b1.y;
            sacc[1][0] += a1.x*b0.x + a1.y*b0.y;
            sacc[1][1] += a1.x*b1.x + a1.y*b1.y;
            sacc[2][0] += a2.x*b0.x + a2.y*b0.y;
            sacc[2][1] += a2.x*b1.x + a2.y*b1.y;
            sacc[3][0] += a3.x*b0.x + a3.y*b0.y;
            sacc[3][1] += a3.x*b1.x + a3.y*b1.y;
        }
        #pragma unroll
        for (int i = 0; i < 4; i++) {
            Ss[ty4+i][tx*2+0] = sacc[i][0] * 0.125f;
            Ss[ty4+i][tx*2+1] = sacc[i][1] * 0.125f;
        }
        __syncthreads();

        // online softmax: warp w handles rows w*8 .. w*8+7, lane = key col
        #pragma unroll
        for (int rr = 0; rr < 8; rr++) {
            int r = warp * 8 + rr;
            float s = Ss[r][lane] + mask[(size_t)(q0 + r) * N_ + kt0 + lane];
            float mx = s;
            #pragma unroll
            for (int o = 16; o; o >>= 1) mx = fmaxf(mx, __shfl_xor_sync(~0u, mx, o));
            float mold = rowm[r];
            float mnew = fmaxf(mold, mx);
            float p = __expf(s - mnew);
            float ps = p;
            #pragma unroll
            for (int o = 16; o; o >>= 1) ps += __shfl_xor_sync(~0u, ps, o);
            if (lane == 0) {
                float corr = __expf(mold - mnew);
                rowl[r] = rowl[r] * corr + ps;
                rowm[r] = mnew;
                rcorr[r] = corr;
            }
            Ss[r][lane] = p;
        }
        __syncthreads();

        // O = O*corr + P.V   (thread: rows ty4..+3, hd cols tx*4..+3)
        float c0 = rcorr[ty4+0], c1 = rcorr[ty4+1], c2 = rcorr[ty4+2], c3 = rcorr[ty4+3];
        #pragma unroll
        for (int c = 0; c < 4; c++) {
            acc[0][c] *= c0; acc[1][c] *= c1; acc[2][c] *= c2; acc[3][c] *= c3;
        }
        #pragma unroll
        for (int j = 0; j < 32; j++) {
            float4 v = *(const float4*)&Vs[j][tx*4];
            float p0 = Ss[ty4+0][j];
            float p1 = Ss[ty4+1][j];
            float p2 = Ss[ty4+2][j];
            float p3 = Ss[ty4+3][j];
            acc[0][0] += p0*v.x; acc[0][1] += p0*v.y; acc[0][2] += p0*v.z; acc[0][3] += p0*v.w;
            acc[1][0] += p1*v.x; acc[1][1] += p1*v.y; acc[1][2] += p1*v.z; acc[1][3] += p1*v.w;
            acc[2][0] += p2*v.x; acc[2][1] += p2*v.y; acc[2][2] += p2*v.z; acc[2][3] += p2*v.w;
            acc[3][0] += p3*v.x; acc[3][1] += p3*v.y; acc[3][2] += p3*v.z; acc[3][3] += p3*v.w;
        }
        __syncthreads();   // protects Ks/Vs/Ss/rcorr for next tile
    }

    // normalize and write to (B, N, H*hd)
    #pragma unroll
    for (int i = 0; i < 4; i++) {
        float inv = 1.f / rowl[ty4 + i];
        size_t o = ((size_t)b * N_ + (q0 + ty4 + i)) * C_ + h * HD_ + tx * 4;
        g_O[o + 0] = acc[i][0] * inv;
        g_O[o + 1] = acc[i][1] * inv;
        g_O[o + 2] = acc[i][2] * inv;
        g_O[o + 3] = acc[i][3] * inv;
    }
}

// ---------------------------------------------------------------------------
extern "C" void kernel_launch(void* const* d_in, const int* in_sizes, int n_in,
                              void* d_out, int out_size)
{
    const float* x      = (const float*)d_in[0];
    const float* fc     = (const float*)d_in[1];
    const float* fs     = (const float*)d_in[2];
    const float* mask   = (const float*)d_in[3];
    const float* w_qkv  = (const float*)d_in[4];
    const float* w_proj = (const float*)d_in[5];
    const float* b_proj = (const float*)d_in[6];
    const float* q_g    = (const float*)d_in[7];
    const float* k_g    = (const float*)d_in[8];
    float* out = (float*)d_out;

    // 1) qkv = x @ w_qkv^T, scattered into Q/K/V (B,H,N,hd)
    dim3 g1(3 * C_ / 128, (B_ * N_) / 128);   // 24 x 32
    gemm128<0><<<g1, 256>>>(x, w_qkv, nullptr, nullptr);

    // 2) RMSNorm + RoPE on Q and K
    rmsrope<<<(B_ * H_ * N_) / 8, 256>>>(fc, fs, q_g, k_g);

    // 3) attention -> g_O (B,N,C)
    attn_kernel<<<dim3(N_ / 64, H_, B_), 256>>>(mask);

    // 4) out = g_O @ w_proj^T + b_proj
    dim3 g2(C_ / 128, (B_ * N_) / 128);       // 8 x 32
    gemm128<1><<<g2, 256>>>(nullptr, w_proj, b_proj, out);
}

// round 4
// speedup vs baseline: 1.0561x; 1.0561x over previous
#include <cuda_runtime.h>
#include <math.h>

#define B_  2
#define N_  2048
#define C_  1024
#define H_  16
#define HD_ 64

// Scratch (allocation-free: device globals). 4 x 16MB = 64MB.
__device__ float g_Q[B_*H_*N_*HD_];
__device__ float g_K[B_*H_*N_*HD_];
__device__ float g_V[B_*H_*N_*HD_];
__device__ float g_O[B_*N_*C_];

// ---------------------------------------------------------------------------
// Tiled SGEMM: C[m,d] = sum_k A[m,k] * W[d,k]  (both row-major, K-contig)
// BM=BN=128, BK=16, 256 threads, 8x8 micro-tile per thread.
// MODE 0: A = x (param), epilogue scatters into g_Q/g_K/g_V.
// MODE 1: A = g_O,       epilogue adds bias, writes outp[m*C_+d].
// ---------------------------------------------------------------------------
template<int MODE>
__global__ __launch_bounds__(256)
void gemm128(const float* __restrict__ Ain, const float* __restrict__ W,
             const float* __restrict__ bias, float* __restrict__ outp)
{
    const float* A = (MODE == 0) ? Ain : g_O;
    const int K = C_;

    __shared__ float As[16][128];
    __shared__ float Bs[16][128];

    int tid = threadIdx.x;
    int m0 = blockIdx.y * 128;
    int n0 = blockIdx.x * 128;
    int ty = tid / 16;        // 0..15 -> rows ty*8..ty*8+7
    int tx = tid % 16;        // 0..15 -> cols tx*8..tx*8+7

    // Load assignment: each thread loads 8 floats (2 float4) of A and W.
    int lr = tid >> 1;            // row within 128-tile
    int lc = (tid & 1) * 8;       // 0 or 8 within 16-wide k slab
    const float* aptr = A + (size_t)(m0 + lr) * K + lc;
    const float* bptr = W + (size_t)(n0 + lr) * K + lc;

    float acc[8][8];
    #pragma unroll
    for (int i = 0; i < 8; i++)
        #pragma unroll
        for (int j = 0; j < 8; j++) acc[i][j] = 0.f;

    for (int kt = 0; kt < K; kt += 16) {
        float4 a0 = *(const float4*)(aptr + kt);
        float4 a1 = *(const float4*)(aptr + kt + 4);
        float4 b0 = *(const float4*)(bptr + kt);
        float4 b1 = *(const float4*)(bptr + kt + 4);
        __syncthreads();
        As[lc+0][lr] = a0.x; As[lc+1][lr] = a0.y; As[lc+2][lr] = a0.z; As[lc+3][lr] = a0.w;
        As[lc+4][lr] = a1.x; As[lc+5][lr] = a1.y; As[lc+6][lr] = a1.z; As[lc+7][lr] = a1.w;
        Bs[lc+0][lr] = b0.x; Bs[lc+1][lr] = b0.y; Bs[lc+2][lr] = b0.z; Bs[lc+3][lr] = b0.w;
        Bs[lc+4][lr] = b1.x; Bs[lc+5][lr] = b1.y; Bs[lc+6][lr] = b1.z; Bs[lc+7][lr] = b1.w;
        __syncthreads();

        #pragma unroll
        for (int kk = 0; kk < 16; kk++) {
            float4 af0 = *(const float4*)&As[kk][ty*8];
            float4 af1 = *(const float4*)&As[kk][ty*8+4];
            float4 bf0 = *(const float4*)&Bs[kk][tx*8];
            float4 bf1 = *(const float4*)&Bs[kk][tx*8+4];
            float a[8] = {af0.x, af0.y, af0.z, af0.w, af1.x, af1.y, af1.z, af1.w};
            float bfr[8] = {bf0.x, bf0.y, bf0.z, bf0.w, bf1.x, bf1.y, bf1.z, bf1.w};
            #pragma unroll
            for (int i = 0; i < 8; i++)
                #pragma unroll
                for (int j = 0; j < 8; j++)
                    acc[i][j] += a[i] * bfr[j];
        }
    }

    if (MODE == 0) {
        #pragma unroll
        for (int i = 0; i < 8; i++) {
            int m = m0 + ty*8 + i;
            int b = m >> 11;          // / N_
            int n = m & (N_ - 1);
            #pragma unroll
            for (int j = 0; j < 8; j++) {
                int d = n0 + tx*8 + j;
                int which = d >> 10;          // 0=q,1=k,2=v
                int h = (d >> 6) & (H_ - 1);
                int e = d & (HD_ - 1);
                float* dst = (which == 0) ? g_Q : (which == 1) ? g_K : g_V;
                dst[((size_t)(b*H_ + h) * N_ + n) * HD_ + e] = acc[i][j];
            }
        }
    } else {
        #pragma unroll
        for (int i = 0; i < 8; i++) {
            int m = m0 + ty*8 + i;
            #pragma unroll
            for (int j = 0; j < 8; j++) {
                int d = n0 + tx*8 + j;
                outp[(size_t)m * C_ + d] = acc[i][j] + bias[d];
            }
        }
    }
}

// ---------------------------------------------------------------------------
// Fused per-head RMSNorm + RoPE for Q and K. One warp per (b,h,n) row.
// Lane l owns elements (2l, 2l+1) -> the rotate_half pair lives in one lane.
// ---------------------------------------------------------------------------
__global__ __launch_bounds__(256)
void rmsrope(const float* __restrict__ fc, const float* __restrict__ fs,
             const float* __restrict__ qg, const float* __restrict__ kg)
{
    int warp = threadIdx.x >> 5;
    int lane = threadIdx.x & 31;
    int row = blockIdx.x * 8 + warp;        // 0 .. B*H*N-1 in (b,h,n) order
    int b = row >> 15;                      // / (H_*N_)
    int n = row & (N_ - 1);

    size_t base = (size_t)row * HD_;
    size_t fb = ((size_t)(b * N_) + n) * HD_ + 2*lane;

    float2 fcv = *(const float2*)&fc[fb];
    float2 fsv = *(const float2*)&fs[fb];
    float2 qgv = *(const float2*)&qg[2*lane];
    float2 kgv = *(const float2*)&kg[2*lane];

    // Q
    {
        float2 q = *(const float2*)&g_Q[base + 2*lane];
        float ss = q.x*q.x + q.y*q.y;
        #pragma unroll
        for (int o = 16; o; o >>= 1) ss += __shfl_xor_sync(~0u, ss, o);
        float inv = 8.f / fmaxf(sqrtf(ss), 1e-12f);   // sqrt(HD)=8
        float nx = q.x * inv * qgv.x;
        float ny = q.y * inv * qgv.y;
        float2 o;
        o.x = nx * fcv.x - ny * fsv.x;
        o.y = ny * fcv.y + nx * fsv.y;
        *(float2*)&g_Q[base + 2*lane] = o;
    }
    // K
    {
        float2 k = *(const float2*)&g_K[base + 2*lane];
        float ss = k.x*k.x + k.y*k.y;
        #pragma unroll
        for (int o = 16; o; o >>= 1) ss += __shfl_xor_sync(~0u, ss, o);
        float inv = 8.f / fmaxf(sqrtf(ss), 1e-12f);
        float nx = k.x * inv * kgv.x;
        float ny = k.y * inv * kgv.y;
        float2 o;
        o.x = nx * fcv.x - ny * fsv.x;
        o.y = ny * fcv.y + nx * fsv.y;
        *(float2*)&g_K[base + 2*lane] = o;
    }
}

// ---------------------------------------------------------------------------
// Flash-style attention. Block = 64 q-rows of one (b,h). 32-key tiles.
// Online softmax with running max/sum; register O-accumulator 4x4/thread.
// Writes O directly in (B, N, H*hd) layout for the projection GEMM.
// ---------------------------------------------------------------------------
__global__ __launch_bounds__(256)
void attn_kernel(const float* __restrict__ mask)
{
    int q0 = blockIdx.x * 64;
    int h  = blockIdx.y;
    int b  = blockIdx.z;

    __shared__ float Qs[64][64];
    __shared__ float Ks[32][66];   // pad 66: conflict-free float2 reads
    __shared__ float Vs[32][64];
    __shared__ float Ss[64][33];
    __shared__ float rowm[64], rowl[64], rcorr[64];

    int tid = threadIdx.x;
    int ty = tid / 16, tx = tid % 16;
    int lane = tid & 31, warp = tid >> 5;
    int ty4 = ty * 4;

    size_t hb = (size_t)(b * H_ + h) * N_ * HD_;

    #pragma unroll
    for (int s = 0; s < 16; s++) {
        int idx = tid + s * 256;
        int r = idx >> 6, e = idx & 63;
        Qs[r][e] = g_Q[hb + (size_t)(q0 + r) * HD_ + e];
    }
    if (tid < 64) { rowm[tid] = -3.0e38f; rowl[tid] = 0.f; }

    float acc[4][4];
    #pragma unroll
    for (int i = 0; i < 4; i++)
        #pragma unroll
        for (int c = 0; c < 4; c++) acc[i][c] = 0.f;

    __syncthreads();

    for (int kt0 = 0; kt0 < N_; kt0 += 32) {
        // load K,V tiles (coalesced)
        #pragma unroll
        for (int s = 0; s < 8; s++) {
            int idx = tid + s * 256;
            int r = idx >> 6, e = idx & 63;
            size_t g = hb + (size_t)(kt0 + r) * HD_ + e;
            Ks[r][e] = g_K[g];
            Vs[r][e] = g_V[g];
        }
        __syncthreads();

        // S = (Q * scale) . K^T   (64 x 32 tile; thread: 4 rows x 2 cols)
        float sacc[4][2] = {{0.f,0.f},{0.f,0.f},{0.f,0.f},{0.f,0.f}};
        #pragma unroll 8
        for (int e = 0; e < 64; e += 2) {
            float2 a0 = *(const float2*)&Qs[ty4+0][e];
            float2 a1 = *(const float2*)&Qs[ty4+1][e];
            float2 a2 = *(const float2*)&Qs[ty4+2][e];
            float2 a3 = *(const float2*)&Qs[ty4+3][e];
            float2 b0 = *(const float2*)&Ks[tx*2+0][e];
            float2 b1 = *(const float2*)&Ks[tx*2+1][e];
            sacc[0][0] += a0.x*b0.x + a0.y*b0.y;
            sacc[0][1] += a0.x*b1.x + a0.y*b1.y;
            sacc[1][0] += a1.x*b0.x + a1.y*b0.y;
            sacc[1][1] += a1.x*b1.x + a1.y*b1.y;
            sacc[2][0] += a2.x*b0.x + a2.y*b0.y;
            sacc[2][1] += a2.x*b1.x + a2.y*b1.y;
            sacc[3][0] += a3.x*b0.x + a3.y*b0.y;
            sacc[3][1] += a3.x*b1.x + a3.y*b1.y;
        }
        #pragma unroll
        for (int i = 0; i < 4; i++) {
            Ss[ty4+i][tx*2+0] = sacc[i][0] * 0.125f;
            Ss[ty4+i][tx*2+1] = sacc[i][1] * 0.125f;
        }
        __syncthreads();

        // online softmax: warp w handles rows w*8 .. w*8+7, lane = key col
        #pragma unroll
        for (int rr = 0; rr < 8; rr++) {
            int r = warp * 8 + rr;
            float s = Ss[r][lane] + mask[(size_t)(q0 + r) * N_ + kt0 + lane];
            float mx = s;
            #pragma unroll
            for (int o = 16; o; o >>= 1) mx = fmaxf(mx, __shfl_xor_sync(~0u, mx, o));
            float mold = rowm[r];
            float mnew = fmaxf(mold, mx);
            float p = __expf(s - mnew);
            float ps = p;
            #pragma unroll
            for (int o = 16; o; o >>= 1) ps += __shfl_xor_sync(~0u, ps, o);
            if (lane == 0) {
                float corr = __expf(mold - mnew);
                rowl[r] = rowl[r] * corr + ps;
                rowm[r] = mnew;
                rcorr[r] = corr;
            }
            Ss[r][lane] = p;
        }
        __syncthreads();

        // O = O*corr + P.V   (thread: rows ty4..+3, hd cols tx*4..+3)
        float c0 = rcorr[ty4+0], c1 = rcorr[ty4+1], c2 = rcorr[ty4+2], c3 = rcorr[ty4+3];
        #pragma unroll
        for (int c = 0; c < 4; c++) {
            acc[0][c] *= c0; acc[1][c] *= c1; acc[2][c] *= c2; acc[3][c] *= c3;
        }
        #pragma unroll
        for (int j = 0; j < 32; j++) {
            float4 v = *(const float4*)&Vs[j][tx*4];
            float p0 = Ss[ty4+0][j];
            float p1 = Ss[ty4+1][j];
            float p2 = Ss[ty4+2][j];
            float p3 = Ss[ty4+3][j];
            acc[0][0] += p0*v.x; acc[0][1] += p0*v.y; acc[0][2] += p0*v.z; acc[0][3] += p0*v.w;
            acc[1][0] += p1*v.x; acc[1][1] += p1*v.y; acc[1][2] += p1*v.z; acc[1][3] += p1*v.w;
            acc[2][0] += p2*v.x; acc[2][1] += p2*v.y; acc[2][2] += p2*v.z; acc[2][3] += p2*v.w;
            acc[3][0] += p3*v.x; acc[3][1] += p3*v.y; acc[3][2] += p3*v.z; acc[3][3] += p3*v.w;
        }
        __syncthreads();   // protects Ks/Vs/Ss/rcorr for next tile
    }

    // normalize and write to (B, N, H*hd)
    #pragma unroll
    for (int i = 0; i < 4; i++) {
        float inv = 1.f / rowl[ty4 + i];
        size_t o = ((size_t)b * N_ + (q0 + ty4 + i)) * C_ + h * HD_ + tx * 4;
        g_O[o + 0] = acc[i][0] * inv;
        g_O[o + 1] = acc[i][1] * inv;
        g_O[o + 2] = acc[i][2] * inv;
        g_O[o + 3] = acc[i][3] * inv;
    }
}

// ---------------------------------------------------------------------------
extern "C" void kernel_launch(void* const* d_in, const int* in_sizes, int n_in,
                              void* d_out, int out_size)
{
    const float* x      = (const float*)d_in[0];
    const float* fc     = (const float*)d_in[1];
    const float* fs     = (const float*)d_in[2];
    const float* mask   = (const float*)d_in[3];
    const float* w_qkv  = (const float*)d_in[4];
    const float* w_proj = (const float*)d_in[5];
    const float* b_proj = (const float*)d_in[6];
    const float* q_g    = (const float*)d_in[7];
    const float* k_g    = (const float*)d_in[8];
    float* out = (float*)d_out;

    // 1) qkv = x @ w_qkv^T, scattered into Q/K/V (B,H,N,hd)
    dim3 g1(3 * C_ / 128, (B_ * N_) / 128);   // 24 x 32
    gemm128<0><<<g1, 256>>>(x, w_qkv, nullptr, nullptr);

    // 2) RMSNorm + RoPE on Q and K
    rmsrope<<<(B_ * H_ * N_) / 8, 256>>>(fc, fs, q_g, k_g);

    // 3) attention -> g_O (B,N,C)
    attn_kernel<<<dim3(N_ / 64, H_, B_), 256>>>(mask);

    // 4) out = g_O @ w_proj^T + b_proj
    dim3 g2(C_ / 128, (B_ * N_) / 128);       // 8 x 32
    gemm128<1><<<g2, 256>>>(nullptr, w_proj, b_proj, out);
}

// round 9
// speedup vs baseline: 2.9496x; 2.7930x over previous
#include <cuda_runtime.h>
#include <cuda_bf16.h>
#include <cstdint>
#include <math.h>

#define B_  2
#define N_  2048
#define C_  1024
#define H_  16
#define HD_ 64

// ---------------- scratch (allocation-free device globals) ----------------
__device__ float         g_Qf[B_*H_*N_*HD_];
__device__ float         g_Kf[B_*H_*N_*HD_];
__device__ __nv_bfloat16 g_Qh[B_*H_*N_*HD_], g_Ql[B_*H_*N_*HD_];
__device__ __nv_bfloat16 g_Kh[B_*H_*N_*HD_], g_Kl[B_*H_*N_*HD_];
__device__ __nv_bfloat16 g_Vth[B_*H_*HD_*N_], g_Vtl[B_*H_*HD_*N_]; // (b,h,e,n)
__device__ __nv_bfloat16 g_Oh[B_*N_*C_],  g_Ol[B_*N_*C_];
__device__ __nv_bfloat16 g_xh[B_*N_*C_],  g_xl[B_*N_*C_];
__device__ __nv_bfloat16 g_wqh[3*C_*C_],  g_wql[3*C_*C_];
__device__ __nv_bfloat16 g_wph[C_*C_],    g_wpl[C_*C_];

// ---------------- helpers -------------------------------------------------
__device__ __forceinline__ uint32_t smem_u32(const void* p){
    uint32_t a;
    asm("{ .reg .u64 t; cvta.to.shared.u64 t, %1; cvt.u32.u64 %0, t; }" : "=r"(a) : "l"(p));
    return a;
}
__device__ __forceinline__ void bsplit(float v, __nv_bfloat16& h, __nv_bfloat16& l){
    h = __float2bfloat16(v);
    l = __float2bfloat16(v - __bfloat162float(h));
}
__device__ __forceinline__ uint32_t pack2(__nv_bfloat16 a, __nv_bfloat16 b){
    __nv_bfloat162 t; t.x = a; t.y = b;
    return *(uint32_t*)&t;
}
__device__ __forceinline__ void ldsm4(uint32_t* r, uint32_t addr){
    asm volatile("ldmatrix.sync.aligned.m8n8.x4.shared.b16 {%0,%1,%2,%3}, [%4];"
        : "=r"(r[0]), "=r"(r[1]), "=r"(r[2]), "=r"(r[3]) : "r"(addr));
}
__device__ __forceinline__ void ldsm2(uint32_t* r, uint32_t addr){
    asm volatile("ldmatrix.sync.aligned.m8n8.x2.shared.b16 {%0,%1}, [%2];"
        : "=r"(r[0]), "=r"(r[1]) : "r"(addr));
}
__device__ __forceinline__ void mma16816(float* d, const uint32_t* a, const uint32_t* b){
    asm volatile("mma.sync.aligned.m16n8k16.row.col.f32.bf16.bf16.f32 "
        "{%0,%1,%2,%3}, {%4,%5,%6,%7}, {%8,%9}, {%0,%1,%2,%3};"
        : "+f"(d[0]), "+f"(d[1]), "+f"(d[2]), "+f"(d[3])
        : "r"(a[0]), "r"(a[1]), "r"(a[2]), "r"(a[3]), "r"(b[0]), "r"(b[1]));
}
// A-fragment (m16k16) ldmatrix.x4 address for this lane
__device__ __forceinline__ uint32_t a4addr(uint32_t base, int row0, int col0, int stride, int lane){
    int g = lane >> 3, r = lane & 7;
    return base + (uint32_t)(((row0 + r + ((g & 1) << 3)) * stride + col0 + ((g >> 1) << 3)) << 1);
}
// B-fragment (k16n8) ldmatrix.x2 address (B stored [n][k], k contiguous)
__device__ __forceinline__ uint32_t b2addr(uint32_t base, int row0, int col0, int stride, int lane){
    int g = (lane >> 3) & 1, r = lane & 7;
    return base + (uint32_t)(((row0 + r) * stride + col0 + (g << 3)) << 1);
}

// ---------------------------------------------------------------------------
// fp32 -> split bf16 (hi, lo).  W: 0=x, 1=w_qkv, 2=w_proj
// ---------------------------------------------------------------------------
template<int W>
__global__ __launch_bounds__(256)
void cvt_split(const float* __restrict__ src){
    int i = blockIdx.x * blockDim.x + threadIdx.x;
    float4 v = ((const float4*)src)[i];
    __nv_bfloat16 h0,l0,h1,l1,h2,l2,h3,l3;
    bsplit(v.x,h0,l0); bsplit(v.y,h1,l1); bsplit(v.z,h2,l2); bsplit(v.w,h3,l3);
    __nv_bfloat16* Hd = (W==0) ? g_xh : (W==1) ? g_wqh : g_wph;
    __nv_bfloat16* Ld = (W==0) ? g_xl : (W==1) ? g_wql : g_wpl;
    ((uint32_t*)Hd)[i*2]   = pack2(h0,h1);  ((uint32_t*)Hd)[i*2+1] = pack2(h2,h3);
    ((uint32_t*)Ld)[i*2]   = pack2(l0,l1);  ((uint32_t*)Ld)[i*2+1] = pack2(l2,l3);
}

// ---------------------------------------------------------------------------
// HMMA GEMM: D[m,n] = sum_k A[m,k]*B[n,k], split-bf16 (3 MMAs per step).
// 128x128 CTA tile, BK=32, 256 threads (8 warps, warp tile 64x32).
// MODE 0: A=x, B=w_qkv -> Q/K fp32 (b,h,n,e) + V split bf16 (b,h,e,n)
// MODE 1: A=O(split),  B=w_proj  -> out + bias
// ---------------------------------------------------------------------------
#define DST 40                       // smem row stride (bf16) -> 80B: ldmatrix conflict-free
#define DG_TILE (128*DST*2)          // 10240 bytes per matrix tile
#define DG_SMEM (4*DG_TILE)          // 40960

template<int MODE>
__global__ __launch_bounds__(256)
void wgemm(const float* __restrict__ bias, float* __restrict__ outp)
{
    extern __shared__ char smem[];
    uint32_t sb = smem_u32(smem);
    const uint32_t sAH = sb, sAL = sb + DG_TILE, sBH = sb + 2*DG_TILE, sBL = sb + 3*DG_TILE;
    const int tid = threadIdx.x, lane = tid & 31, wid = tid >> 5;
    const int wm0 = (wid >> 2) * 64, wn0 = (wid & 3) * 32;
    const int m0 = blockIdx.y * 128, n0 = blockIdx.x * 128;

    const __nv_bfloat16* Ah = MODE ? g_Oh : g_xh;
    const __nv_bfloat16* Al = MODE ? g_Ol : g_xl;
    const __nv_bfloat16* Bh = MODE ? g_wph : g_wqh;
    const __nv_bfloat16* Bl = MODE ? g_wpl : g_wql;

    const int lr = tid >> 1, lk = (tid & 1) * 16;
    const __nv_bfloat16* pah = Ah + (size_t)(m0 + lr) * C_ + lk;
    const __nv_bfloat16* pal = Al + (size_t)(m0 + lr) * C_ + lk;
    const __nv_bfloat16* pbh = Bh + (size_t)(n0 + lr) * C_ + lk;
    const __nv_bfloat16* pbl = Bl + (size_t)(n0 + lr) * C_ + lk;
    char* stA = smem + (lr*DST + lk)*2;

    uint4 ra0, ra1, rb0, rb1, rc0, rc1, rd0, rd1;
    ra0 = *(const uint4*)pah;       ra1 = *(const uint4*)(pah + 8);
    rb0 = *(const uint4*)pal;       rb1 = *(const uint4*)(pal + 8);
    rc0 = *(const uint4*)pbh;       rc1 = *(const uint4*)(pbh + 8);
    rd0 = *(const uint4*)pbl;       rd1 = *(const uint4*)(pbl + 8);

    float acc[4][4][4];
    #pragma unroll
    for (int a = 0; a < 4; a++)
        #pragma unroll
        for (int b = 0; b < 4; b++)
            #pragma unroll
            for (int c = 0; c < 4; c++) acc[a][b][c] = 0.f;

    for (int s = 0; s < C_/32; s++) {
        __syncthreads();
        *(uint4*)(stA + 0*DG_TILE)      = ra0; *(uint4*)(stA + 0*DG_TILE + 16) = ra1;
        *(uint4*)(stA + 1*DG_TILE)      = rb0; *(uint4*)(stA + 1*DG_TILE + 16) = rb1;
        *(uint4*)(stA + 2*DG_TILE)      = rc0; *(uint4*)(stA + 2*DG_TILE + 16) = rc1;
        *(uint4*)(stA + 3*DG_TILE)      = rd0; *(uint4*)(stA + 3*DG_TILE + 16) = rd1;
        __syncthreads();
        if (s + 1 < C_/32) {
            pah += 32; pal += 32; pbh += 32; pbl += 32;
            ra0 = *(const uint4*)pah;  ra1 = *(const uint4*)(pah + 8);
            rb0 = *(const uint4*)pal;  rb1 = *(const uint4*)(pal + 8);
            rc0 = *(const uint4*)pbh;  rc1 = *(const uint4*)(pbh + 8);
            rd0 = *(const uint4*)pbl;  rd1 = *(const uint4*)(pbl + 8);
        }
        #pragma unroll
        for (int ks = 0; ks < 32; ks += 16) {
            uint32_t fbh[4][2], fbl[4][2];
            #pragma unroll
            for (int nt = 0; nt < 4; nt++) {
                ldsm2(fbh[nt], b2addr(sBH, wn0 + nt*8, ks, DST, lane));
                ldsm2(fbl[nt], b2addr(sBL, wn0 + nt*8, ks, DST, lane));
            }
            #pragma unroll
            for (int mt = 0; mt < 4; mt++) {
                uint32_t fah[4], fal[4];
                ldsm4(fah, a4addr(sAH, wm0 + mt*16, ks, DST, lane));
                ldsm4(fal, a4addr(sAL, wm0 + mt*16, ks, DST, lane));
                #pragma unroll
                for (int nt = 0; nt < 4; nt++) {
                    mma16816(acc[mt][nt], fah, fbh[nt]);
                    mma16816(acc[mt][nt], fah, fbl[nt]);
                    mma16816(acc[mt][nt], fal, fbh[nt]);
                }
            }
        }
    }

    // epilogue: lane holds (r0,c),(r0,c+1),(r1,c),(r1,c+1) per (mt,nt)
    const int lr2 = lane >> 2, lc2 = (lane & 3) * 2;
    #pragma unroll
    for (int mt = 0; mt < 4; mt++) {
        int mA = m0 + wm0 + mt*16 + lr2;
        #pragma unroll
        for (int nt = 0; nt < 4; nt++) {
            int d0 = n0 + wn0 + nt*8 + lc2;
            if (MODE == 0) {
                #pragma unroll
                for (int q = 0; q < 4; q++) {
                    int mm = mA + (q >> 1) * 8;
                    int dd = d0 + (q & 1);
                    int bb = mm >> 11, nn = mm & (N_-1);
                    int which = dd >> 10, hh = (dd >> 6) & (H_-1), ee = dd & (HD_-1);
                    float v = acc[mt][nt][q];
                    if (which == 0)      g_Qf[((size_t)(bb*H_+hh)*N_ + nn)*HD_ + ee] = v;
                    else if (which == 1) g_Kf[((size_t)(bb*H_+hh)*N_ + nn)*HD_ + ee] = v;
                    else {
                        __nv_bfloat16 hb, lb; bsplit(v, hb, lb);
                        size_t vo = ((size_t)(bb*H_+hh)*HD_ + ee)*N_ + nn;
                        g_Vth[vo] = hb; g_Vtl[vo] = lb;
                    }
                }
            } else {
                float2 bv = *(const float2*)(bias + d0);
                float2 o0; o0.x = acc[mt][nt][0] + bv.x; o0.y = acc[mt][nt][1] + bv.y;
                float2 o1; o1.x = acc[mt][nt][2] + bv.x; o1.y = acc[mt][nt][3] + bv.y;
                *(float2*)(outp + (size_t)mA * C_ + d0)       = o0;
                *(float2*)(outp + (size_t)(mA + 8) * C_ + d0) = o1;
            }
        }
    }
}

// ---------------------------------------------------------------------------
// RMSNorm + RoPE (fp32 in -> split bf16 out; 1/8 softmax scale folded into Q)
// ---------------------------------------------------------------------------
__global__ __launch_bounds__(256)
void rmsrope(const float* __restrict__ fc, const float* __restrict__ fs,
             const float* __restrict__ qg, const float* __restrict__ kg)
{
    int warp = threadIdx.x >> 5, lane = threadIdx.x & 31;
    int row = blockIdx.x * 8 + warp;
    int b = row >> 15, n = row & (N_ - 1);
    size_t base = (size_t)row * HD_;
    size_t fb = ((size_t)(b * N_) + n) * HD_ + 2*lane;

    float2 fcv = *(const float2*)&fc[fb];
    float2 fsv = *(const float2*)&fs[fb];
    float2 qgv = *(const float2*)&qg[2*lane];
    float2 kgv = *(const float2*)&kg[2*lane];

    {
        float2 q = *(const float2*)&g_Qf[base + 2*lane];
        float ss = q.x*q.x + q.y*q.y;
        #pragma unroll
        for (int o = 16; o; o >>= 1) ss += __shfl_xor_sync(~0u, ss, o);
        float inv = 8.f / fmaxf(sqrtf(ss), 1e-12f);
        float nx = q.x * inv * qgv.x, ny = q.y * inv * qgv.y;
        float ox = (nx * fcv.x - ny * fsv.x) * 0.125f;
        float oy = (ny * fcv.y + nx * fsv.y) * 0.125f;
        __nv_bfloat16 h0,l0,h1,l1; bsplit(ox,h0,l0); bsplit(oy,h1,l1);
        *(uint32_t*)(g_Qh + base + 2*lane) = pack2(h0,h1);
        *(uint32_t*)(g_Ql + base + 2*lane) = pack2(l0,l1);
    }
    {
        float2 k = *(const float2*)&g_Kf[base + 2*lane];
        float ss = k.x*k.x + k.y*k.y;
        #pragma unroll
        for (int o = 16; o; o >>= 1) ss += __shfl_xor_sync(~0u, ss, o);
        float inv = 8.f / fmaxf(sqrtf(ss), 1e-12f);
        float nx = k.x * inv * kgv.x, ny = k.y * inv * kgv.y;
        float ox = nx * fcv.x - ny * fsv.x;
        float oy = ny * fcv.y + nx * fsv.y;
        __nv_bfloat16 h0,l0,h1,l1; bsplit(ox,h0,l0); bsplit(oy,h1,l1);
        *(uint32_t*)(g_Kh + base + 2*lane) = pack2(h0,h1);
        *(uint32_t*)(g_Kl + base + 2*lane) = pack2(l0,l1);
    }
}

// ---------------------------------------------------------------------------
// HMMA flash attention. CTA = 128 q-rows x one (b,h). 128-key tiles.
// 256 threads, 8 warps. S warp-tile 64x32 (keys); O warp-tile 64x16 (e).
// ---------------------------------------------------------------------------
#define QST 72       // Q/K smem stride (bf16); 144B rows -> conflict-free ldmatrix
#define VST 136      // V/P smem stride (bf16); 272B rows -> conflict-free
#define OQH 0
#define OQL 18432
#define OKH 36864
#define OKL 55296
#define OVH 73728
#define OVL 91136
#define OPH 108544
#define OPL 143360
#define OWR 178176   // float[4][128] cross-warp reductions
#define ORM 180224   // float[128] running max
#define ORL 180736   // float[128] running sum
#define ORC 181248   // float[128] correction
#define A_SMEM 181760

__global__ __launch_bounds__(256)
void attn_wm(const float* __restrict__ mask)
{
    extern __shared__ char smem[];
    uint32_t sb = smem_u32(smem);
    float* wred  = (float*)(smem + OWR);
    float* rowm  = (float*)(smem + ORM);
    float* rowl  = (float*)(smem + ORL);
    float* rcorr = (float*)(smem + ORC);

    const int tid = threadIdx.x, lane = tid & 31, wid = tid >> 5;
    const int wm0 = (wid >> 2) * 64, wn0 = (wid & 3) * 32, wne = (wid & 3) * 16;
    const int lr = lane >> 2, lc2 = (lane & 3) * 2;
    const int q0 = blockIdx.x * 128, h = blockIdx.y, b = blockIdx.z;
    const size_t bh = (size_t)(b * H_ + h);

    { // Q tile (persistent)
        int r = tid >> 1, off = (tid & 1) * 32;
        const uint4* qh = (const uint4*)(g_Qh + (bh*N_ + q0 + r) * HD_ + off);
        const uint4* ql = (const uint4*)(g_Ql + (bh*N_ + q0 + r) * HD_ + off);
        uint4* dh = (uint4*)(smem + OQH + (r*QST + off)*2);
        uint4* dl = (uint4*)(smem + OQL + (r*QST + off)*2);
        #pragma unroll
        for (int i = 0; i < 4; i++) { dh[i] = qh[i]; dl[i] = ql[i]; }
    }
    if (tid < 128) { rowm[tid] = -3.0e38f; rowl[tid] = 0.f; }

    float oacc[4][2][4];
    #pragma unroll
    for (int a = 0; a < 4; a++)
        #pragma unroll
        for (int c = 0; c < 2; c++)
            #pragma unroll
            for (int q = 0; q < 4; q++) oacc[a][c][q] = 0.f;

    for (int kt = 0; kt < N_; kt += 128) {
        { // K tile [128 key][64 e], V tile [64 e][128 key]
            int r = tid >> 1, off = (tid & 1) * 32;
            const uint4* kh = (const uint4*)(g_Kh + (bh*N_ + kt + r) * HD_ + off);
            const uint4* kl = (const uint4*)(g_Kl + (bh*N_ + kt + r) * HD_ + off);
            uint4* dkh = (uint4*)(smem + OKH + (r*QST + off)*2);
            uint4* dkl = (uint4*)(smem + OKL + (r*QST + off)*2);
            int e = tid >> 2, of2 = (tid & 3) * 32;
            const uint4* vh = (const uint4*)(g_Vth + (bh*HD_ + e)*N_ + kt + of2);
            const uint4* vl = (const uint4*)(g_Vtl + (bh*HD_ + e)*N_ + kt + of2);
            uint4* dvh = (uint4*)(smem + OVH + (e*VST + of2)*2);
            uint4* dvl = (uint4*)(smem + OVL + (e*VST + of2)*2);
            #pragma unroll
            for (int i = 0; i < 4; i++) {
                dkh[i] = kh[i]; dkl[i] = kl[i];
                dvh[i] = vh[i]; dvl[i] = vl[i];
            }
        }
        __syncthreads();

        // ---- S = Q . K^T  (warp tile 64x32) ----
        float sacc[4][4][4];
        #pragma unroll
        for (int a = 0; a < 4; a++)
            #pragma unroll
            for (int c = 0; c < 4; c++)
                #pragma unroll
                for (int q = 0; q < 4; q++) sacc[a][c][q] = 0.f;
        #pragma unroll
        for (int ks = 0; ks < 64; ks += 16) {
            uint32_t fbh[4][2], fbl[4][2];
            #pragma unroll
            for (int nt = 0; nt < 4; nt++) {
                ldsm2(fbh[nt], b2addr(sb + OKH, wn0 + nt*8, ks, QST, lane));
                ldsm2(fbl[nt], b2addr(sb + OKL, wn0 + nt*8, ks, QST, lane));
            }
            #pragma unroll
            for (int mt = 0; mt < 4; mt++) {
                uint32_t fah[4], fal[4];
                ldsm4(fah, a4addr(sb + OQH, wm0 + mt*16, ks, QST, lane));
                ldsm4(fal, a4addr(sb + OQL, wm0 + mt*16, ks, QST, lane));
                #pragma unroll
                for (int nt = 0; nt < 4; nt++) {
                    mma16816(sacc[mt][nt], fah, fbh[nt]);
                    mma16816(sacc[mt][nt], fah, fbl[nt]);
                    mma16816(sacc[mt][nt], fal, fbh[nt]);
                }
            }
        }

        // ---- add mask, per-lane row maxima ----
        float lmax[8];
        #pragma unroll
        for (int i = 0; i < 8; i++) lmax[i] = -3.0e38f;
        #pragma unroll
        for (int mt = 0; mt < 4; mt++) {
            int r0 = wm0 + mt*16 + lr;
            #pragma unroll
            for (int nt = 0; nt < 4; nt++) {
                const float* mp = mask + (size_t)(q0 + r0)*N_ + kt + wn0 + nt*8 + lc2;
                float2 m0v = *(const float2*)mp;
                float2 m1v = *(const float2*)(mp + 8*N_);
                sacc[mt][nt][0] += m0v.x; sacc[mt][nt][1] += m0v.y;
                sacc[mt][nt][2] += m1v.x; sacc[mt][nt][3] += m1v.y;
                lmax[mt*2]   = fmaxf(lmax[mt*2],   fmaxf(sacc[mt][nt][0], sacc[mt][nt][1]));
                lmax[mt*2+1] = fmaxf(lmax[mt*2+1], fmaxf(sacc[mt][nt][2], sacc[mt][nt][3]));
            }
        }
        #pragma unroll
        for (int i = 0; i < 8; i++) {
            lmax[i] = fmaxf(lmax[i], __shfl_xor_sync(~0u, lmax[i], 1));
            lmax[i] = fmaxf(lmax[i], __shfl_xor_sync(~0u, lmax[i], 2));
        }
        if ((lane & 3) == 0) {
            #pragma unroll
            for (int i = 0; i < 8; i++)
                wred[(wid & 3)*128 + wm0 + (i>>1)*16 + lr + (i&1)*8] = lmax[i];
        }
        __syncthreads();
        if (tid < 128) {
            float gm = fmaxf(fmaxf(wred[tid], wred[128+tid]), fmaxf(wred[256+tid], wred[384+tid]));
            float mo = rowm[tid], mn = fmaxf(mo, gm);
            rowm[tid] = mn; rcorr[tid] = __expf(mo - mn);
        }
        __syncthreads();

        // ---- exp, split P to bf16 hi/lo in smem, row sums ----
        float lsum[8];
        #pragma unroll
        for (int i = 0; i < 8; i++) lsum[i] = 0.f;
        #pragma unroll
        for (int mt = 0; mt < 4; mt++) {
            int r0 = wm0 + mt*16 + lr;
            float mr0 = rowm[r0], mr1 = rowm[r0 + 8];
            #pragma unroll
            for (int nt = 0; nt < 4; nt++) {
                float p0 = __expf(sacc[mt][nt][0] - mr0);
                float p1 = __expf(sacc[mt][nt][1] - mr0);
                float p2 = __expf(sacc[mt][nt][2] - mr1);
                float p3 = __expf(sacc[mt][nt][3] - mr1);
                lsum[mt*2]   += p0 + p1;
                lsum[mt*2+1] += p2 + p3;
                __nv_bfloat16 h0,l0,h1,l1,h2,l2,h3,l3;
                bsplit(p0,h0,l0); bsplit(p1,h1,l1); bsplit(p2,h2,l2); bsplit(p3,h3,l3);
                int col = wn0 + nt*8 + lc2;
                *(uint32_t*)(smem + OPH + (r0*VST + col)*2)       = pack2(h0,h1);
                *(uint32_t*)(smem + OPH + ((r0+8)*VST + col)*2)   = pack2(h2,h3);
                *(uint32_t*)(smem + OPL + (r0*VST + col)*2)       = pack2(l0,l1);
                *(uint32_t*)(smem + OPL + ((r0+8)*VST + col)*2)   = pack2(l2,l3);
            }
        }
        #pragma unroll
        for (int i = 0; i < 8; i++) {
            lsum[i] += __shfl_xor_sync(~0u, lsum[i], 1);
            lsum[i] += __shfl_xor_sync(~0u, lsum[i], 2);
        }
        if ((lane & 3) == 0) {
            #pragma unroll
            for (int i = 0; i < 8; i++)
                wred[(wid & 3)*128 + wm0 + (i>>1)*16 + lr + (i&1)*8] = lsum[i];
        }
        __syncthreads();
        if (tid < 128)
            rowl[tid] = rowl[tid]*rcorr[tid] + wred[tid] + wred[128+tid] + wred[256+tid] + wred[384+tid];
        __syncthreads();

        // ---- O *= corr; O += P . V  (warp tile 64x16 over e) ----
        #pragma unroll
        for (int mt = 0; mt < 4; mt++) {
            float c0 = rcorr[wm0 + mt*16 + lr];
            float c1 = rcorr[wm0 + mt*16 + lr + 8];
            #pragma unroll
            for (int nt = 0; nt < 2; nt++) {
                oacc[mt][nt][0] *= c0; oacc[mt][nt][1] *= c0;
                oacc[mt][nt][2] *= c1; oacc[mt][nt][3] *= c1;
            }
        }
        #pragma unroll
        for (int kb = 0; kb < 8; kb++) {
            uint32_t fvh[2][2], fvl[2][2];
            #pragma unroll
            for (int nt = 0; nt < 2; nt++) {
                ldsm2(fvh[nt], b2addr(sb + OVH, wne + nt*8, kb*16, VST, lane));
                ldsm2(fvl[nt], b2addr(sb + OVL, wne + nt*8, kb*16, VST, lane));
            }
            #pragma unroll
            for (int mt = 0; mt < 4; mt++) {
                uint32_t fph[4], fpl[4];
                ldsm4(fph, a4addr(sb + OPH, wm0 + mt*16, kb*16, VST, lane));
                ldsm4(fpl, a4addr(sb + OPL, wm0 + mt*16, kb*16, VST, lane));
                #pragma unroll
                for (int nt = 0; nt < 2; nt++) {
                    mma16816(oacc[mt][nt], fph, fvh[nt]);
                    mma16816(oacc[mt][nt], fph, fvl[nt]);
                    mma16816(oacc[mt][nt], fpl, fvh[nt]);
                }
            }
        }
        __syncthreads();
    }

    // ---- normalize, split, write O (b, n, h*64+e) ----
    #pragma unroll
    for (int mt = 0; mt < 4; mt++) {
        int r0 = wm0 + mt*16 + lr;
        float i0 = 1.f / rowl[r0], i1 = 1.f / rowl[r0 + 8];
        #pragma unroll
        for (int nt = 0; nt < 2; nt++) {
            int e = wne + nt*8 + lc2;
            __nv_bfloat16 h0,l0,h1,l1;
            bsplit(oacc[mt][nt][0]*i0, h0, l0); bsplit(oacc[mt][nt][1]*i0, h1, l1);
            *(uint32_t*)(g_Oh + ((size_t)b*N_ + q0 + r0)*C_ + h*HD_ + e) = pack2(h0,h1);
            *(uint32_t*)(g_Ol + ((size_t)b*N_ + q0 + r0)*C_ + h*HD_ + e) = pack2(l0,l1);
            bsplit(oacc[mt][nt][2]*i1, h0, l0); bsplit(oacc[mt][nt][3]*i1, h1, l1);
            *(uint32_t*)(g_Oh + ((size_t)b*N_ + q0 + r0 + 8)*C_ + h*HD_ + e) = pack2(h0,h1);
            *(uint32_t*)(g_Ol + ((size_t)b*N_ + q0 + r0 + 8)*C_ + h*HD_ + e) = pack2(l0,l1);
        }
    }
}

// ---------------------------------------------------------------------------
extern "C" void kernel_launch(void* const* d_in, const int* in_sizes, int n_in,
                              void* d_out, int out_size)
{
    const float* x      = (const float*)d_in[0];
    const float* fc     = (const float*)d_in[1];
    const float* fs     = (const float*)d_in[2];
    const float* mask   = (const float*)d_in[3];
    const float* w_qkv  = (const float*)d_in[4];
    const float* w_proj = (const float*)d_in[5];
    const float* b_proj = (const float*)d_in[6];
    const float* q_g    = (const float*)d_in[7];
    const float* k_g    = (const float*)d_in[8];
    float* out = (float*)d_out;

    cudaFuncSetAttribute(wgemm<0>, cudaFuncAttributeMaxDynamicSharedMemorySize, DG_SMEM);
    cudaFuncSetAttribute(wgemm<1>, cudaFuncAttributeMaxDynamicSharedMemorySize, DG_SMEM);
    cudaFuncSetAttribute(attn_wm,  cudaFuncAttributeMaxDynamicSharedMemorySize, A_SMEM);

    cvt_split<0><<<B_*N_*C_/1024, 256>>>(x);
    cvt_split<1><<<3*C_*C_/1024, 256>>>(w_qkv);
    cvt_split<2><<<C_*C_/1024, 256>>>(w_proj);

    wgemm<0><<<dim3(3*C_/128, B_*N_/128), 256, DG_SMEM>>>(nullptr, nullptr);
    rmsrope<<<(B_*H_*N_)/8, 256>>>(fc, fs, q_g, k_g);
    attn_wm<<<dim3(N_/128, H_, B_), 256, A_SMEM>>>(mask);
    wgemm<1><<<dim3(C_/128, B_*N_/128), 256, DG_SMEM>>>(b_proj, out);
}

// round 10
// speedup vs baseline: 3.0323x; 1.0280x over previous
#include <cuda_runtime.h>
#include <cuda_bf16.h>
#include <cstdint>
#include <math.h>

#define B_  2
#define N_  2048
#define C_  1024
#define H_  16
#define HD_ 64

// ---------------- scratch (allocation-free device globals) ----------------
__device__ float         g_Qf[B_*H_*N_*HD_];
__device__ float         g_Kf[B_*H_*N_*HD_];
__device__ __nv_bfloat16 g_Qh[B_*H_*N_*HD_], g_Ql[B_*H_*N_*HD_];
__device__ __nv_bfloat16 g_Kh[B_*H_*N_*HD_], g_Kl[B_*H_*N_*HD_];
__device__ __nv_bfloat16 g_Vth[B_*H_*HD_*N_], g_Vtl[B_*H_*HD_*N_]; // (b,h,e,n)
__device__ __nv_bfloat16 g_Oh[B_*N_*C_],  g_Ol[B_*N_*C_];
__device__ __nv_bfloat16 g_xh[B_*N_*C_],  g_xl[B_*N_*C_];
__device__ __nv_bfloat16 g_wqh[3*C_*C_],  g_wql[3*C_*C_];
__device__ __nv_bfloat16 g_wph[C_*C_],    g_wpl[C_*C_];

// ---------------- helpers -------------------------------------------------
__device__ __forceinline__ uint32_t smem_u32(const void* p){
    uint32_t a;
    asm("{ .reg .u64 t; cvta.to.shared.u64 t, %1; cvt.u32.u64 %0, t; }" : "=r"(a) : "l"(p));
    return a;
}
__device__ __forceinline__ void bsplit(float v, __nv_bfloat16& h, __nv_bfloat16& l){
    h = __float2bfloat16(v);
    l = __float2bfloat16(v - __bfloat162float(h));
}
__device__ __forceinline__ uint32_t pack2(__nv_bfloat16 a, __nv_bfloat16 b){
    __nv_bfloat162 t; t.x = a; t.y = b;
    return *(uint32_t*)&t;
}
__device__ __forceinline__ uint32_t packf(float a, float b){
    return pack2(__float2bfloat16(a), __float2bfloat16(b));
}
__device__ __forceinline__ uint32_t packfl(float a, float b){
    __nv_bfloat16 ha = __float2bfloat16(a), hb = __float2bfloat16(b);
    return pack2(__float2bfloat16(a - __bfloat162float(ha)),
                 __float2bfloat16(b - __bfloat162float(hb)));
}
__device__ __forceinline__ void ldsm4(uint32_t* r, uint32_t addr){
    asm volatile("ldmatrix.sync.aligned.m8n8.x4.shared.b16 {%0,%1,%2,%3}, [%4];"
        : "=r"(r[0]), "=r"(r[1]), "=r"(r[2]), "=r"(r[3]) : "r"(addr));
}
__device__ __forceinline__ void ldsm2(uint32_t* r, uint32_t addr){
    asm volatile("ldmatrix.sync.aligned.m8n8.x2.shared.b16 {%0,%1}, [%2];"
        : "=r"(r[0]), "=r"(r[1]) : "r"(addr));
}
__device__ __forceinline__ void mma16816(float* d, const uint32_t* a, const uint32_t* b){
    asm volatile("mma.sync.aligned.m16n8k16.row.col.f32.bf16.bf16.f32 "
        "{%0,%1,%2,%3}, {%4,%5,%6,%7}, {%8,%9}, {%0,%1,%2,%3};"
        : "+f"(d[0]), "+f"(d[1]), "+f"(d[2]), "+f"(d[3])
        : "r"(a[0]), "r"(a[1]), "r"(a[2]), "r"(a[3]), "r"(b[0]), "r"(b[1]));
}
// A-fragment (m16k16) ldmatrix.x4 address
__device__ __forceinline__ uint32_t a4addr(uint32_t base, int row0, int col0, int stride, int lane){
    int g = lane >> 3, r = lane & 7;
    return base + (uint32_t)(((row0 + r + ((g & 1) << 3)) * stride + col0 + ((g >> 1) << 3)) << 1);
}
// B-fragment ldmatrix.x4: two n-blocks (n0, n0+8), both k-halves of k16 block at col0
__device__ __forceinline__ uint32_t b4addr(uint32_t base, int n0, int col0, int stride, int lane){
    int g = lane >> 3, r = lane & 7;
    return base + (uint32_t)(((n0 + ((g >> 1) << 3) + r) * stride + col0 + ((g & 1) << 3)) << 1);
}
// B-fragment (k16n8) ldmatrix.x2 (single n-block)
__device__ __forceinline__ uint32_t b2addr(uint32_t base, int row0, int col0, int stride, int lane){
    int g = (lane >> 3) & 1, r = lane & 7;
    return base + (uint32_t)(((row0 + r) * stride + col0 + (g << 3)) << 1);
}
__device__ __forceinline__ void cpa16(uint32_t dst, const void* src){
    asm volatile("cp.async.cg.shared.global [%0], [%1], 16;" :: "r"(dst), "l"(src));
}
#define CP_COMMIT() asm volatile("cp.async.commit_group;" ::: "memory")
#define CP_WAIT(N)  asm volatile("cp.async.wait_group %0;" :: "n"(N) : "memory")

// ---------------------------------------------------------------------------
// fp32 -> split bf16 (hi, lo).  W: 0=x, 1=w_qkv, 2=w_proj
// ---------------------------------------------------------------------------
template<int W>
__global__ __launch_bounds__(256)
void cvt_split(const float* __restrict__ src){
    int i = blockIdx.x * blockDim.x + threadIdx.x;
    float4 v = ((const float4*)src)[i];
    __nv_bfloat16* Hd = (W==0) ? g_xh : (W==1) ? g_wqh : g_wph;
    __nv_bfloat16* Ld = (W==0) ? g_xl : (W==1) ? g_wql : g_wpl;
    ((uint32_t*)Hd)[i*2]   = packf(v.x, v.y);  ((uint32_t*)Hd)[i*2+1] = packf(v.z, v.w);
    ((uint32_t*)Ld)[i*2]   = packfl(v.x, v.y); ((uint32_t*)Ld)[i*2+1] = packfl(v.z, v.w);
}

// ---------------------------------------------------------------------------
// HMMA GEMM, 3-stage cp.async pipeline. D[m,n] = sum_k A[m,k]*B[n,k].
// 128x128 CTA tile, BK=32, 256 threads (8 warps, warp tile 64x32).
// ---------------------------------------------------------------------------
#define DST 40                       // smem row stride (bf16): 80B, conflict-free
#define DG_MAT 10240                 // 128*40*2 per matrix
#define DG_STG (4*DG_MAT)            // 40960 per stage
#define DG_SMEM (3*DG_STG)           // 122880

template<int MODE>
__global__ __launch_bounds__(256)
void wgemm(const float* __restrict__ bias, float* __restrict__ outp)
{
    extern __shared__ char smem[];
    uint32_t sb = smem_u32(smem);
    const int tid = threadIdx.x, lane = tid & 31, wid = tid >> 5;
    const int wm0 = (wid >> 2) * 64, wn0 = (wid & 3) * 32;
    const int m0 = blockIdx.y * 128, n0 = blockIdx.x * 128;
    const int NSLAB = C_ / 32;

    const __nv_bfloat16* Ah = MODE ? g_Oh : g_xh;
    const __nv_bfloat16* Al = MODE ? g_Ol : g_xl;
    const __nv_bfloat16* Bh = MODE ? g_wph : g_wqh;
    const __nv_bfloat16* Bl = MODE ? g_wpl : g_wql;

    // cp.async map: 512 16B segs per matrix; thread does 2 per matrix.
    const int r0l = (tid + 0*256) >> 2, s0l = (tid + 0*256) & 3;
    const int r1l = (tid + 1*256) >> 2, s1l = (tid + 1*256) & 3;

    auto issue = [&](int s){
        uint32_t st = sb + (uint32_t)(s % 3) * DG_STG;
        const __nv_bfloat16* srcs[4] = {
            Ah + (size_t)(m0 + r0l) * C_ + s*32 + s0l*8,
            Al + (size_t)(m0 + r0l) * C_ + s*32 + s0l*8,
            Bh + (size_t)(n0 + r0l) * C_ + s*32 + s0l*8,
            Bl + (size_t)(n0 + r0l) * C_ + s*32 + s0l*8 };
        const __nv_bfloat16* srcs1[4] = {
            Ah + (size_t)(m0 + r1l) * C_ + s*32 + s1l*8,
            Al + (size_t)(m0 + r1l) * C_ + s*32 + s1l*8,
            Bh + (size_t)(n0 + r1l) * C_ + s*32 + s1l*8,
            Bl + (size_t)(n0 + r1l) * C_ + s*32 + s1l*8 };
        #pragma unroll
        for (int mtx = 0; mtx < 4; mtx++) {
            cpa16(st + mtx*DG_MAT + (uint32_t)(r0l*80 + s0l*16), srcs[mtx]);
            cpa16(st + mtx*DG_MAT + (uint32_t)(r1l*80 + s1l*16), srcs1[mtx]);
        }
        CP_COMMIT();
    };

    float acc[4][4][4];
    #pragma unroll
    for (int a = 0; a < 4; a++)
        #pragma unroll
        for (int b = 0; b < 4; b++)
            #pragma unroll
            for (int c = 0; c < 4; c++) acc[a][b][c] = 0.f;

    issue(0); issue(1);

    for (int s = 0; s < NSLAB; s++) {
        CP_WAIT(1);
        __syncthreads();
        if (s + 2 < NSLAB) issue(s + 2);
        uint32_t st = sb + (uint32_t)(s % 3) * DG_STG;
        uint32_t sAH = st, sAL = st + DG_MAT, sBH = st + 2*DG_MAT, sBL = st + 3*DG_MAT;
        #pragma unroll
        for (int ks = 0; ks < 32; ks += 16) {
            uint32_t fbh[4][2], fbl[4][2];
            #pragma unroll
            for (int nt = 0; nt < 4; nt++) {
                ldsm2(fbh[nt], b2addr(sBH, wn0 + nt*8, ks, DST, lane));
                ldsm2(fbl[nt], b2addr(sBL, wn0 + nt*8, ks, DST, lane));
            }
            #pragma unroll
            for (int mt = 0; mt < 4; mt++) {
                uint32_t fah[4], fal[4];
                ldsm4(fah, a4addr(sAH, wm0 + mt*16, ks, DST, lane));
                ldsm4(fal, a4addr(sAL, wm0 + mt*16, ks, DST, lane));
                #pragma unroll
                for (int nt = 0; nt < 4; nt++) {
                    mma16816(acc[mt][nt], fah, fbh[nt]);
                    mma16816(acc[mt][nt], fah, fbl[nt]);
                    mma16816(acc[mt][nt], fal, fbh[nt]);
                }
            }
        }
    }

    const int lr2 = lane >> 2, lc2 = (lane & 3) * 2;
    #pragma unroll
    for (int mt = 0; mt < 4; mt++) {
        int mA = m0 + wm0 + mt*16 + lr2;
        #pragma unroll
        for (int nt = 0; nt < 4; nt++) {
            int d0 = n0 + wn0 + nt*8 + lc2;
            if (MODE == 0) {
                #pragma unroll
                for (int q = 0; q < 4; q++) {
                    int mm = mA + (q >> 1) * 8;
                    int dd = d0 + (q & 1);
                    int bb = mm >> 11, nn = mm & (N_-1);
                    int which = dd >> 10, hh = (dd >> 6) & (H_-1), ee = dd & (HD_-1);
                    float v = acc[mt][nt][q];
                    if (which == 0)      g_Qf[((size_t)(bb*H_+hh)*N_ + nn)*HD_ + ee] = v;
                    else if (which == 1) g_Kf[((size_t)(bb*H_+hh)*N_ + nn)*HD_ + ee] = v;
                    else {
                        __nv_bfloat16 hb, lb; bsplit(v, hb, lb);
                        size_t vo = ((size_t)(bb*H_+hh)*HD_ + ee)*N_ + nn;
                        g_Vth[vo] = hb; g_Vtl[vo] = lb;
                    }
                }
            } else {
                float2 bv = *(const float2*)(bias + d0);
                float2 o0; o0.x = acc[mt][nt][0] + bv.x; o0.y = acc[mt][nt][1] + bv.y;
                float2 o1; o1.x = acc[mt][nt][2] + bv.x; o1.y = acc[mt][nt][3] + bv.y;
                *(float2*)(outp + (size_t)mA * C_ + d0)       = o0;
                *(float2*)(outp + (size_t)(mA + 8) * C_ + d0) = o1;
            }
        }
    }
}

// ---------------------------------------------------------------------------
// RMSNorm + RoPE (fp32 in -> split bf16 out; 1/8 softmax scale folded into Q)
// ---------------------------------------------------------------------------
__global__ __launch_bounds__(256)
void rmsrope(const float* __restrict__ fc, const float* __restrict__ fs,
             const float* __restrict__ qg, const float* __restrict__ kg)
{
    int warp = threadIdx.x >> 5, lane = threadIdx.x & 31;
    int row = blockIdx.x * 8 + warp;
    int b = row >> 15, n = row & (N_ - 1);
    size_t base = (size_t)row * HD_;
    size_t fb = ((size_t)(b * N_) + n) * HD_ + 2*lane;

    float2 fcv = *(const float2*)&fc[fb];
    float2 fsv = *(const float2*)&fs[fb];
    float2 qgv = *(const float2*)&qg[2*lane];
    float2 kgv = *(const float2*)&kg[2*lane];

    {
        float2 q = *(const float2*)&g_Qf[base + 2*lane];
        float ss = q.x*q.x + q.y*q.y;
        #pragma unroll
        for (int o = 16; o; o >>= 1) ss += __shfl_xor_sync(~0u, ss, o);
        float inv = 8.f / fmaxf(sqrtf(ss), 1e-12f);
        float nx = q.x * inv * qgv.x, ny = q.y * inv * qgv.y;
        float ox = (nx * fcv.x - ny * fsv.x) * 0.125f;
        float oy = (ny * fcv.y + nx * fsv.y) * 0.125f;
        *(uint32_t*)(g_Qh + base + 2*lane) = packf(ox, oy);
        *(uint32_t*)(g_Ql + base + 2*lane) = packfl(ox, oy);
    }
    {
        float2 k = *(const float2*)&g_Kf[base + 2*lane];
        float ss = k.x*k.x + k.y*k.y;
        #pragma unroll
        for (int o = 16; o; o >>= 1) ss += __shfl_xor_sync(~0u, ss, o);
        float inv = 8.f / fmaxf(sqrtf(ss), 1e-12f);
        float nx = k.x * inv * kgv.x, ny = k.y * inv * kgv.y;
        float ox = nx * fcv.x - ny * fsv.x;
        float oy = ny * fcv.y + nx * fsv.y;
        *(uint32_t*)(g_Kh + base + 2*lane) = packf(ox, oy);
        *(uint32_t*)(g_Kl + base + 2*lane) = packfl(ox, oy);
    }
}

// ---------------------------------------------------------------------------
// FA2-style HMMA flash attention. CTA = 128 q x (b,h), 8 warps.
// Warp owns 16 q-rows x ALL 128 keys -> P stays in registers (S D-frag -> PV
// A-frag repack), warp-local online softmax, Q frags register-resident.
// K/V double-buffered in smem via cp.async.
// ---------------------------------------------------------------------------
#define QST 72        // K smem stride (bf16): 144B rows, conflict-free
#define VST 136       // V smem stride (bf16): 272B rows, conflict-free
#define SKH 0
#define SKL 18432
#define SVH 36864
#define SVL 54272
#define STG_SZ 71680
#define A_SMEM (2*STG_SZ)   // 143360

__global__ __launch_bounds__(256)
void attn_fa(const float* __restrict__ mask)
{
    extern __shared__ char smem[];
    uint32_t sb = smem_u32(smem);
    const int tid = threadIdx.x, lane = tid & 31, wid = tid >> 5;
    const int wq0 = wid * 16;               // warp's q-row block
    const int lr = lane >> 2, lc2 = (lane & 3) * 2;
    const int q0 = blockIdx.x * 128, h = blockIdx.y, b = blockIdx.z;
    const size_t bh = (size_t)(b * H_ + h);
    const int NT = N_ / 128;                // 16 key tiles

    // cp.async maps (4 per thread per matrix)
    auto issue = [&](int t){
        uint32_t st = sb + (uint32_t)((t & 1)) * STG_SZ;
        int kt = t * 128;
        #pragma unroll
        for (int i = 0; i < 4; i++) {
            int idx = tid + i*256;
            int row = idx >> 3, seg = idx & 7;          // K: 128 rows x 8 segs
            const __nv_bfloat16* kh = g_Kh + (bh*N_ + kt + row)*HD_ + seg*8;
            const __nv_bfloat16* kl = g_Kl + (bh*N_ + kt + row)*HD_ + seg*8;
            cpa16(st + SKH + (uint32_t)(row*144 + seg*16), kh);
            cpa16(st + SKL + (uint32_t)(row*144 + seg*16), kl);
            int e = idx >> 4, sg2 = idx & 15;           // V: 64 rows x 16 segs
            const __nv_bfloat16* vh = g_Vth + (bh*HD_ + e)*N_ + kt + sg2*8;
            const __nv_bfloat16* vl = g_Vtl + (bh*HD_ + e)*N_ + kt + sg2*8;
            cpa16(st + SVH + (uint32_t)(e*272 + sg2*16), vh);
            cpa16(st + SVL + (uint32_t)(e*272 + sg2*16), vl);
        }
        CP_COMMIT();
    };

    issue(0);

    // ---- Q frags: stage Q into stage-1 K area, ldmatrix, keep in regs ----
    uint32_t qfh[4][4], qfl[4][4];
    {
        int r = tid >> 1, off = (tid & 1) * 32;
        const uint4* qh = (const uint4*)(g_Qh + (bh*N_ + q0 + r) * HD_ + off);
        const uint4* ql = (const uint4*)(g_Ql + (bh*N_ + q0 + r) * HD_ + off);
        uint4* dh = (uint4*)(smem + STG_SZ + SKH + r*144 + off*2);
        uint4* dl = (uint4*)(smem + STG_SZ + SKL + r*144 + off*2);
        #pragma unroll
        for (int i = 0; i < 4; i++) { dh[i] = qh[i]; dl[i] = ql[i]; }
        __syncthreads();
        #pragma unroll
        for (int ks = 0; ks < 4; ks++) {
            ldsm4(qfh[ks], a4addr(sb + STG_SZ + SKH, wq0, ks*16, QST, lane));
            ldsm4(qfl[ks], a4addr(sb + STG_SZ + SKL, wq0, ks*16, QST, lane));
        }
        __syncthreads();
    }
    issue(1);

    float oacc[8][4];
    #pragma unroll
    for (int e = 0; e < 8; e++)
        #pragma unroll
        for (int q = 0; q < 4; q++) oacc[e][q] = 0.f;
    float m0r = -3.0e38f, m1r = -3.0e38f, l0r = 0.f, l1r = 0.f;

    const float* mrow0 = mask + (size_t)(q0 + wq0 + lr) * N_;
    const float* mrow1 = mrow0 + 8 * N_;

    for (int t = 0; t < NT; t++) {
        CP_WAIT(1);
        __syncthreads();
        uint32_t st = sb + (uint32_t)(t & 1) * STG_SZ;
        int kt = t * 128;

        // ---- S = Q.K^T : sacc[nt][4], nt = 16 key 8-blocks ----
        float sacc[16][4];
        #pragma unroll
        for (int nt = 0; nt < 16; nt++)
            #pragma unroll
            for (int q = 0; q < 4; q++) sacc[nt][q] = 0.f;
        #pragma unroll
        for (int ks = 0; ks < 4; ks++) {
            #pragma unroll
            for (int np = 0; np < 8; np++) {
                uint32_t fh[4], fl[4];
                ldsm4(fh, b4addr(st + SKH, np*16, ks*16, QST, lane));
                ldsm4(fl, b4addr(st + SKL, np*16, ks*16, QST, lane));
                mma16816(sacc[np*2],   qfh[ks], fh);
                mma16816(sacc[np*2],   qfh[ks], fl);
                mma16816(sacc[np*2],   qfl[ks], fh);
                mma16816(sacc[np*2+1], qfh[ks], fh+2);
                mma16816(sacc[np*2+1], qfh[ks], fl+2);
                mma16816(sacc[np*2+1], qfl[ks], fh+2);
            }
        }

        // ---- mask add + warp-local online softmax ----
        float mt0 = -3.0e38f, mt1 = -3.0e38f;
        #pragma unroll
        for (int nt = 0; nt < 16; nt++) {
            const float* mp = mrow0 + kt + nt*8 + lc2;
            float2 ma = *(const float2*)mp;
            float2 mb = *(const float2*)(mrow1 + kt + nt*8 + lc2);
            sacc[nt][0] += ma.x; sacc[nt][1] += ma.y;
            sacc[nt][2] += mb.x; sacc[nt][3] += mb.y;
            mt0 = fmaxf(mt0, fmaxf(sacc[nt][0], sacc[nt][1]));
            mt1 = fmaxf(mt1, fmaxf(sacc[nt][2], sacc[nt][3]));
        }
        mt0 = fmaxf(mt0, __shfl_xor_sync(~0u, mt0, 1));
        mt0 = fmaxf(mt0, __shfl_xor_sync(~0u, mt0, 2));
        mt1 = fmaxf(mt1, __shfl_xor_sync(~0u, mt1, 1));
        mt1 = fmaxf(mt1, __shfl_xor_sync(~0u, mt1, 2));
        float mn0 = fmaxf(m0r, mt0), mn1 = fmaxf(m1r, mt1);
        float c0 = __expf(m0r - mn0), c1 = __expf(m1r - mn1);
        m0r = mn0; m1r = mn1;

        float s0 = 0.f, s1 = 0.f;
        #pragma unroll
        for (int nt = 0; nt < 16; nt++) {
            sacc[nt][0] = __expf(sacc[nt][0] - mn0);
            sacc[nt][1] = __expf(sacc[nt][1] - mn0);
            sacc[nt][2] = __expf(sacc[nt][2] - mn1);
            sacc[nt][3] = __expf(sacc[nt][3] - mn1);
            s0 += sacc[nt][0] + sacc[nt][1];
            s1 += sacc[nt][2] + sacc[nt][3];
        }
        s0 += __shfl_xor_sync(~0u, s0, 1); s0 += __shfl_xor_sync(~0u, s0, 2);
        s1 += __shfl_xor_sync(~0u, s1, 1); s1 += __shfl_xor_sync(~0u, s1, 2);
        l0r = l0r * c0 + s0;
        l1r = l1r * c1 + s1;

        #pragma unroll
        for (int e = 0; e < 8; e++) {
            oacc[e][0] *= c0; oacc[e][1] *= c0;
            oacc[e][2] *= c1; oacc[e][3] *= c1;
        }

        // ---- PV: P frags repacked from sacc, V frags from smem ----
        #pragma unroll
        for (int kb = 0; kb < 8; kb++) {
            uint32_t ph[4], pl[4];
            ph[0] = packf (sacc[2*kb][0],   sacc[2*kb][1]);
            ph[1] = packf (sacc[2*kb][2],   sacc[2*kb][3]);
            ph[2] = packf (sacc[2*kb+1][0], sacc[2*kb+1][1]);
            ph[3] = packf (sacc[2*kb+1][2], sacc[2*kb+1][3]);
            pl[0] = packfl(sacc[2*kb][0],   sacc[2*kb][1]);
            pl[1] = packfl(sacc[2*kb][2],   sacc[2*kb][3]);
            pl[2] = packfl(sacc[2*kb+1][0], sacc[2*kb+1][1]);
            pl[3] = packfl(sacc[2*kb+1][2], sacc[2*kb+1][3]);
            #pragma unroll
            for (int ep = 0; ep < 4; ep++) {
                uint32_t vh[4], vl[4];
                ldsm4(vh, b4addr(st + SVH, ep*16, kb*16, VST, lane));
                ldsm4(vl, b4addr(st + SVL, ep*16, kb*16, VST, lane));
                mma16816(oacc[ep*2],   ph, vh);
                mma16816(oacc[ep*2],   ph, vl);
                mma16816(oacc[ep*2],   pl, vh);
                mma16816(oacc[ep*2+1], ph, vh+2);
                mma16816(oacc[ep*2+1], ph, vl+2);
                mma16816(oacc[ep*2+1], pl, vh+2);
            }
        }
        __syncthreads();
        if (t + 2 < NT) issue(t + 2);
    }

    // ---- normalize + write O (b, n, h*64+e), split bf16 ----
    float i0 = 1.f / l0r, i1 = 1.f / l1r;
    size_t ro0 = ((size_t)b * N_ + q0 + wq0 + lr) * C_ + h * HD_;
    size_t ro1 = ro0 + (size_t)8 * C_;
    #pragma unroll
    for (int e = 0; e < 8; e++) {
        int ec = e*8 + lc2;
        float a0 = oacc[e][0]*i0, a1 = oacc[e][1]*i0;
        float a2 = oacc[e][2]*i1, a3 = oacc[e][3]*i1;
        *(uint32_t*)(g_Oh + ro0 + ec) = packf(a0, a1);
        *(uint32_t*)(g_Ol + ro0 + ec) = packfl(a0, a1);
        *(uint32_t*)(g_Oh + ro1 + ec) = packf(a2, a3);
        *(uint32_t*)(g_Ol + ro1 + ec) = packfl(a2, a3);
    }
}

// ---------------------------------------------------------------------------
extern "C" void kernel_launch(void* const* d_in, const int* in_sizes, int n_in,
                              void* d_out, int out_size)
{
    const float* x      = (const float*)d_in[0];
    const float* fc     = (const float*)d_in[1];
    const float* fs     = (const float*)d_in[2];
    const float* mask   = (const float*)d_in[3];
    const float* w_qkv  = (const float*)d_in[4];
    const float* w_proj = (const float*)d_in[5];
    const float* b_proj = (const float*)d_in[6];
    const float* q_g    = (const float*)d_in[7];
    const float* k_g    = (const float*)d_in[8];
    float* out = (float*)d_out;

    cudaFuncSetAttribute(wgemm<0>, cudaFuncAttributeMaxDynamicSharedMemorySize, DG_SMEM);
    cudaFuncSetAttribute(wgemm<1>, cudaFuncAttributeMaxDynamicSharedMemorySize, DG_SMEM);
    cudaFuncSetAttribute(attn_fa,  cudaFuncAttributeMaxDynamicSharedMemorySize, A_SMEM);

    cvt_split<0><<<B_*N_*C_/1024, 256>>>(x);
    cvt_split<1><<<3*C_*C_/1024, 256>>>(w_qkv);
    cvt_split<2><<<C_*C_/1024, 256>>>(w_proj);

    wgemm<0><<<dim3(3*C_/128, B_*N_/128), 256, DG_SMEM>>>(nullptr, nullptr);
    rmsrope<<<(B_*H_*N_)/8, 256>>>(fc, fs, q_g, k_g);
    attn_fa<<<dim3(N_/128, H_, B_), 256, A_SMEM>>>(mask);
    wgemm<1><<<dim3(C_/128, B_*N_/128), 256, DG_SMEM>>>(b_proj, out);
}

// round 13
// speedup vs baseline: 3.8093x; 1.2563x over previous
#include <cuda_runtime.h>
#include <cuda_bf16.h>
#include <cstdint>
#include <math.h>

#define B_  2
#define N_  2048
#define C_  1024
#define H_  16
#define HD_ 64

// ---------------- scratch (allocation-free device globals) ----------------
__device__ float         g_Qf[B_*H_*N_*HD_];
__device__ float         g_Kf[B_*H_*N_*HD_];
__device__ __nv_bfloat16 g_Qh[B_*H_*N_*HD_], g_Ql[B_*H_*N_*HD_];
__device__ __nv_bfloat16 g_Kh[B_*H_*N_*HD_], g_Kl[B_*H_*N_*HD_];
__device__ __nv_bfloat16 g_Vth[B_*H_*HD_*N_], g_Vtl[B_*H_*HD_*N_]; // (b,h,e,n)
__device__ __nv_bfloat16 g_Oh[B_*N_*C_],  g_Ol[B_*N_*C_];
__device__ __nv_bfloat16 g_xh[B_*N_*C_],  g_xl[B_*N_*C_];
__device__ __nv_bfloat16 g_wqh[3*C_*C_],  g_wql[3*C_*C_];
__device__ __nv_bfloat16 g_wph[C_*C_],    g_wpl[C_*C_];

// ---------------- helpers -------------------------------------------------
__device__ __forceinline__ uint32_t smem_u32(const void* p){
    uint32_t a;
    asm("{ .reg .u64 t; cvta.to.shared.u64 t, %1; cvt.u32.u64 %0, t; }" : "=r"(a) : "l"(p));
    return a;
}
__device__ __forceinline__ void bsplit(float v, __nv_bfloat16& h, __nv_bfloat16& l){
    h = __float2bfloat16(v);
    l = __float2bfloat16(v - __bfloat162float(h));
}
__device__ __forceinline__ uint32_t pack2(__nv_bfloat16 a, __nv_bfloat16 b){
    __nv_bfloat162 t; t.x = a; t.y = b;
    return *(uint32_t*)&t;
}
__device__ __forceinline__ uint32_t packf(float a, float b){
    return pack2(__float2bfloat16(a), __float2bfloat16(b));
}
__device__ __forceinline__ uint32_t packfl(float a, float b){
    __nv_bfloat16 ha = __float2bfloat16(a), hb = __float2bfloat16(b);
    return pack2(__float2bfloat16(a - __bfloat162float(ha)),
                 __float2bfloat16(b - __bfloat162float(hb)));
}
__device__ __forceinline__ void ldsm4(uint32_t* r, uint32_t addr){
    asm volatile("ldmatrix.sync.aligned.m8n8.x4.shared.b16 {%0,%1,%2,%3}, [%4];"
        : "=r"(r[0]), "=r"(r[1]), "=r"(r[2]), "=r"(r[3]) : "r"(addr));
}
__device__ __forceinline__ void ldsm2(uint32_t* r, uint32_t addr){
    asm volatile("ldmatrix.sync.aligned.m8n8.x2.shared.b16 {%0,%1}, [%2];"
        : "=r"(r[0]), "=r"(r[1]) : "r"(addr));
}
__device__ __forceinline__ void mma16816(float* d, const uint32_t* a, const uint32_t* b){
    asm volatile("mma.sync.aligned.m16n8k16.row.col.f32.bf16.bf16.f32 "
        "{%0,%1,%2,%3}, {%4,%5,%6,%7}, {%8,%9}, {%0,%1,%2,%3};"
        : "+f"(d[0]), "+f"(d[1]), "+f"(d[2]), "+f"(d[3])
        : "r"(a[0]), "r"(a[1]), "r"(a[2]), "r"(a[3]), "r"(b[0]), "r"(b[1]));
}
// A-fragment (m16k16) ldmatrix.x4 address
__device__ __forceinline__ uint32_t a4addr(uint32_t base, int row0, int col0, int stride, int lane){
    int g = lane >> 3, r = lane & 7;
    return base + (uint32_t)(((row0 + r + ((g & 1) << 3)) * stride + col0 + ((g >> 1) << 3)) << 1);
}
// B-fragment ldmatrix.x4: two n-blocks (n0, n0+8), both k-halves of k16 block at col0
__device__ __forceinline__ uint32_t b4addr(uint32_t base, int n0, int col0, int stride, int lane){
    int g = lane >> 3, r = lane & 7;
    return base + (uint32_t)(((n0 + ((g >> 1) << 3) + r) * stride + col0 + ((g & 1) << 3)) << 1);
}
// B-fragment (k16n8) ldmatrix.x2 (single n-block)
__device__ __forceinline__ uint32_t b2addr(uint32_t base, int row0, int col0, int stride, int lane){
    int g = (lane >> 3) & 1, r = lane & 7;
    return base + (uint32_t)(((row0 + r) * stride + col0 + (g << 3)) << 1);
}
__device__ __forceinline__ void cpa16(uint32_t dst, const void* src){
    asm volatile("cp.async.cg.shared.global [%0], [%1], 16;" :: "r"(dst), "l"(src));
}
#define CP_COMMIT() asm volatile("cp.async.commit_group;" ::: "memory")
#define CP_WAIT(N)  asm volatile("cp.async.wait_group %0;" :: "n"(N) : "memory")

// ---------------------------------------------------------------------------
// fp32 -> split bf16 (hi, lo).  W: 0=x, 1=w_qkv, 2=w_proj
// ---------------------------------------------------------------------------
template<int W>
__global__ __launch_bounds__(256)
void cvt_split(const float* __restrict__ src){
    int i = blockIdx.x * blockDim.x + threadIdx.x;
    float4 v = ((const float4*)src)[i];
    __nv_bfloat16* Hd = (W==0) ? g_xh : (W==1) ? g_wqh : g_wph;
    __nv_bfloat16* Ld = (W==0) ? g_xl : (W==1) ? g_wql : g_wpl;
    ((uint32_t*)Hd)[i*2]   = packf(v.x, v.y);  ((uint32_t*)Hd)[i*2+1] = packf(v.z, v.w);
    ((uint32_t*)Ld)[i*2]   = packfl(v.x, v.y); ((uint32_t*)Ld)[i*2+1] = packfl(v.z, v.w);
}

// ---------------------------------------------------------------------------
// HMMA GEMM, 2-stage cp.async pipeline, 2 CTAs/SM. D[m,n] = sum_k A[m,k]*B[n,k]
// 128x128 CTA tile, BK=32, 256 threads (8 warps, warp tile 64x32).
// ---------------------------------------------------------------------------
#define DST 40                       // smem row stride (bf16): 80B, conflict-free
#define DG_MAT 10240                 // 128*40*2 per matrix
#define DG_STG (4*DG_MAT)            // 40960 per stage
#define DG_SMEM (2*DG_STG)           // 81920 -> 2 CTAs/SM

template<int MODE>
__global__ __launch_bounds__(256, 2)
void wgemm(const float* __restrict__ bias, float* __restrict__ outp)
{
    extern __shared__ char smem[];
    uint32_t sb = smem_u32(smem);
    const int tid = threadIdx.x, lane = tid & 31, wid = tid >> 5;
    const int wm0 = (wid >> 2) * 64, wn0 = (wid & 3) * 32;
    const int m0 = blockIdx.y * 128, n0 = blockIdx.x * 128;
    const int NSLAB = C_ / 32;

    const __nv_bfloat16* Ah = MODE ? g_Oh : g_xh;
    const __nv_bfloat16* Al = MODE ? g_Ol : g_xl;
    const __nv_bfloat16* Bh = MODE ? g_wph : g_wqh;
    const __nv_bfloat16* Bl = MODE ? g_wpl : g_wql;

    const int r0l = (tid + 0*256) >> 2, s0l = (tid + 0*256) & 3;
    const int r1l = (tid + 1*256) >> 2, s1l = (tid + 1*256) & 3;

    auto issue = [&](int s){
        uint32_t st = sb + (uint32_t)(s & 1) * DG_STG;
        const __nv_bfloat16* srcs[4] = {
            Ah + (size_t)(m0 + r0l) * C_ + s*32 + s0l*8,
            Al + (size_t)(m0 + r0l) * C_ + s*32 + s0l*8,
            Bh + (size_t)(n0 + r0l) * C_ + s*32 + s0l*8,
            Bl + (size_t)(n0 + r0l) * C_ + s*32 + s0l*8 };
        const __nv_bfloat16* srcs1[4] = {
            Ah + (size_t)(m0 + r1l) * C_ + s*32 + s1l*8,
            Al + (size_t)(m0 + r1l) * C_ + s*32 + s1l*8,
            Bh + (size_t)(n0 + r1l) * C_ + s*32 + s1l*8,
            Bl + (size_t)(n0 + r1l) * C_ + s*32 + s1l*8 };
        #pragma unroll
        for (int mtx = 0; mtx < 4; mtx++) {
            cpa16(st + mtx*DG_MAT + (uint32_t)(r0l*80 + s0l*16), srcs[mtx]);
            cpa16(st + mtx*DG_MAT + (uint32_t)(r1l*80 + s1l*16), srcs1[mtx]);
        }
        CP_COMMIT();
    };

    float acc[4][4][4];
    #pragma unroll
    for (int a = 0; a < 4; a++)
        #pragma unroll
        for (int b = 0; b < 4; b++)
            #pragma unroll
            for (int c = 0; c < 4; c++) acc[a][b][c] = 0.f;

    issue(0); issue(1);

    for (int s = 0; s < NSLAB; s++) {
        CP_WAIT(1);
        __syncthreads();
        uint32_t st = sb + (uint32_t)(s & 1) * DG_STG;
        uint32_t sAH = st, sAL = st + DG_MAT, sBH = st + 2*DG_MAT, sBL = st + 3*DG_MAT;
        #pragma unroll
        for (int ks = 0; ks < 32; ks += 16) {
            uint32_t fbh[4][2], fbl[4][2];
            #pragma unroll
            for (int nt = 0; nt < 4; nt++) {
                ldsm2(fbh[nt], b2addr(sBH, wn0 + nt*8, ks, DST, lane));
                ldsm2(fbl[nt], b2addr(sBL, wn0 + nt*8, ks, DST, lane));
            }
            #pragma unroll
            for (int mt = 0; mt < 4; mt++) {
                uint32_t fah[4], fal[4];
                ldsm4(fah, a4addr(sAH, wm0 + mt*16, ks, DST, lane));
                ldsm4(fal, a4addr(sAL, wm0 + mt*16, ks, DST, lane));
                #pragma unroll
                for (int nt = 0; nt < 4; nt++) {
                    mma16816(acc[mt][nt], fah, fbh[nt]);
                    mma16816(acc[mt][nt], fah, fbl[nt]);
                    mma16816(acc[mt][nt], fal, fbh[nt]);
                }
            }
        }
        __syncthreads();
        if (s + 2 < NSLAB) issue(s + 2);
    }

    const int lr2 = lane >> 2, lc2 = (lane & 3) * 2;
    #pragma unroll
    for (int mt = 0; mt < 4; mt++) {
        int mA = m0 + wm0 + mt*16 + lr2;
        #pragma unroll
        for (int nt = 0; nt < 4; nt++) {
            int d0 = n0 + wn0 + nt*8 + lc2;
            if (MODE == 0) {
                #pragma unroll
                for (int q = 0; q < 4; q++) {
                    int mm = mA + (q >> 1) * 8;
                    int dd = d0 + (q & 1);
                    int bb = mm >> 11, nn = mm & (N_-1);
                    int which = dd >> 10, hh = (dd >> 6) & (H_-1), ee = dd & (HD_-1);
                    float v = acc[mt][nt][q];
                    if (which == 0)      g_Qf[((size_t)(bb*H_+hh)*N_ + nn)*HD_ + ee] = v;
                    else if (which == 1) g_Kf[((size_t)(bb*H_+hh)*N_ + nn)*HD_ + ee] = v;
                    else {
                        __nv_bfloat16 hb, lb; bsplit(v, hb, lb);
                        size_t vo = ((size_t)(bb*H_+hh)*HD_ + ee)*N_ + nn;
                        g_Vth[vo] = hb; g_Vtl[vo] = lb;
                    }
                }
            } else {
                float2 bv = *(const float2*)(bias + d0);
                float2 o0; o0.x = acc[mt][nt][0] + bv.x; o0.y = acc[mt][nt][1] + bv.y;
                float2 o1; o1.x = acc[mt][nt][2] + bv.x; o1.y = acc[mt][nt][3] + bv.y;
                *(float2*)(outp + (size_t)mA * C_ + d0)       = o0;
                *(float2*)(outp + (size_t)(mA + 8) * C_ + d0) = o1;
            }
        }
    }
}

// ---------------------------------------------------------------------------
// RMSNorm + RoPE (fp32 in -> split bf16 out; 1/8 softmax scale folded into Q)
// ---------------------------------------------------------------------------
__global__ __launch_bounds__(256)
void rmsrope(const float* __restrict__ fc, const float* __restrict__ fs,
             const float* __restrict__ qg, const float* __restrict__ kg)
{
    int warp = threadIdx.x >> 5, lane = threadIdx.x & 31;
    int row = blockIdx.x * 8 + warp;
    int b = row >> 15, n = row & (N_ - 1);
    size_t base = (size_t)row * HD_;
    size_t fb = ((size_t)(b * N_) + n) * HD_ + 2*lane;

    float2 fcv = *(const float2*)&fc[fb];
    float2 fsv = *(const float2*)&fs[fb];
    float2 qgv = *(const float2*)&qg[2*lane];
    float2 kgv = *(const float2*)&kg[2*lane];

    {
        float2 q = *(const float2*)&g_Qf[base + 2*lane];
        float ss = q.x*q.x + q.y*q.y;
        #pragma unroll
        for (int o = 16; o; o >>= 1) ss += __shfl_xor_sync(~0u, ss, o);
        float inv = 8.f / fmaxf(sqrtf(ss), 1e-12f);
        float nx = q.x * inv * qgv.x, ny = q.y * inv * qgv.y;
        float ox = (nx * fcv.x - ny * fsv.x) * 0.125f;
        float oy = (ny * fcv.y + nx * fsv.y) * 0.125f;
        *(uint32_t*)(g_Qh + base + 2*lane) = packf(ox, oy);
        *(uint32_t*)(g_Ql + base + 2*lane) = packfl(ox, oy);
    }
    {
        float2 k = *(const float2*)&g_Kf[base + 2*lane];
        float ss = k.x*k.x + k.y*k.y;
        #pragma unroll
        for (int o = 16; o; o >>= 1) ss += __shfl_xor_sync(~0u, ss, o);
        float inv = 8.f / fmaxf(sqrtf(ss), 1e-12f);
        float nx = k.x * inv * kgv.x, ny = k.y * inv * kgv.y;
        float ox = nx * fcv.x - ny * fsv.x;
        float oy = ny * fcv.y + nx * fsv.y;
        *(uint32_t*)(g_Kh + base + 2*lane) = packf(ox, oy);
        *(uint32_t*)(g_Kl + base + 2*lane) = packfl(ox, oy);
    }
}

// ---------------------------------------------------------------------------
// FA2-style HMMA flash attention. CTA = 128 q x (b,h), 8 warps, 64-key tiles,
// double-buffered K/V via cp.async, 2 CTAs/SM. Warp = 16 q-rows x all 64 keys:
// P stays in registers, warp-local online softmax, Q frags register-resident.
// ---------------------------------------------------------------------------
#define AST 72        // K/V smem stride (bf16): 144B rows, conflict-free
#define SKH 0
#define SKL 9216
#define SVH 18432
#define SVL 27648
#define STG_SZ 36864
#define A_SMEM (2*STG_SZ)   // 73728 -> 2 CTAs/SM

__global__ __launch_bounds__(256, 2)
void attn_fa(const float* __restrict__ mask)
{
    extern __shared__ char smem[];
    uint32_t sb = smem_u32(smem);
    const int tid = threadIdx.x, lane = tid & 31, wid = tid >> 5;
    const int wq0 = wid * 16;               // warp's q-row block
    const int lr = lane >> 2, lc2 = (lane & 3) * 2;
    const int q0 = blockIdx.x * 128, h = blockIdx.y, b = blockIdx.z;
    const size_t bh = (size_t)(b * H_ + h);
    const int NT = N_ / 64;                 // 32 key tiles

    // cp.async per stage: K 64x8segs x2 + V 64x8segs x2 = 2048 segs, 8/thread
    auto issue = [&](int t){
        uint32_t st = sb + (uint32_t)(t & 1) * STG_SZ;
        int kt = t * 64;
        #pragma unroll
        for (int i = 0; i < 2; i++) {
            int idx = tid + i*256;
            int row = idx >> 3, seg = idx & 7;
            const __nv_bfloat16* kh = g_Kh + (bh*N_ + kt + row)*HD_ + seg*8;
            const __nv_bfloat16* kl = g_Kl + (bh*N_ + kt + row)*HD_ + seg*8;
            cpa16(st + SKH + (uint32_t)(row*144 + seg*16), kh);
            cpa16(st + SKL + (uint32_t)(row*144 + seg*16), kl);
            const __nv_bfloat16* vh = g_Vth + (bh*HD_ + row)*N_ + kt + seg*8;
            const __nv_bfloat16* vl = g_Vtl + (bh*HD_ + row)*N_ + kt + seg*8;
            cpa16(st + SVH + (uint32_t)(row*144 + seg*16), vh);
            cpa16(st + SVL + (uint32_t)(row*144 + seg*16), vl);
        }
        CP_COMMIT();
    };

    issue(0);

    // ---- Q frags: stage into stage-1 area (scratch), ldmatrix to regs ----
    uint32_t qfh[4][4], qfl[4][4];
    {
        int r = tid >> 1, off = (tid & 1) * 32;
        const uint4* qh = (const uint4*)(g_Qh + (bh*N_ + q0 + r) * HD_ + off);
        const uint4* ql = (const uint4*)(g_Ql + (bh*N_ + q0 + r) * HD_ + off);
        uint4* dh = (uint4*)(smem + STG_SZ + 0     + r*144 + off*2);
        uint4* dl = (uint4*)(smem + STG_SZ + 18432 + r*144 + off*2);
        #pragma unroll
        for (int i = 0; i < 4; i++) { dh[i] = qh[i]; dl[i] = ql[i]; }
        __syncthreads();
        #pragma unroll
        for (int ks = 0; ks < 4; ks++) {
            ldsm4(qfh[ks], a4addr(sb + STG_SZ + 0,     wq0, ks*16, AST, lane));
            ldsm4(qfl[ks], a4addr(sb + STG_SZ + 18432, wq0, ks*16, AST, lane));
        }
        __syncthreads();
    }
    issue(1);

    float oacc[8][4];
    #pragma unroll
    for (int e = 0; e < 8; e++)
        #pragma unroll
        for (int q = 0; q < 4; q++) oacc[e][q] = 0.f;
    float m0r = -3.0e38f, m1r = -3.0e38f, l0r = 0.f, l1r = 0.f;

    const float* mrow0 = mask + (size_t)(q0 + wq0 + lr) * N_;
    const float* mrow1 = mrow0 + 8 * N_;

    for (int t = 0; t < NT; t++) {
        CP_WAIT(1);
        __syncthreads();
        uint32_t st = sb + (uint32_t)(t & 1) * STG_SZ;
        int kt = t * 64;

        // ---- S = Q.K^T : sacc[nt][4], nt = 8 key 8-blocks ----
        float sacc[8][4];
        #pragma unroll
        for (int nt = 0; nt < 8; nt++)
            #pragma unroll
            for (int q = 0; q < 4; q++) sacc[nt][q] = 0.f;
        #pragma unroll
        for (int ks = 0; ks < 4; ks++) {
            #pragma unroll
            for (int np = 0; np < 4; np++) {
                uint32_t fh[4], fl[4];
                ldsm4(fh, b4addr(st + SKH, np*16, ks*16, AST, lane));
                ldsm4(fl, b4addr(st + SKL, np*16, ks*16, AST, lane));
                mma16816(sacc[np*2],   qfh[ks], fh);
                mma16816(sacc[np*2],   qfh[ks], fl);
                mma16816(sacc[np*2],   qfl[ks], fh);
                mma16816(sacc[np*2+1], qfh[ks], fh+2);
                mma16816(sacc[np*2+1], qfh[ks], fl+2);
                mma16816(sacc[np*2+1], qfl[ks], fh+2);
            }
        }

        // ---- mask add + warp-local online softmax ----
        float mt0 = -3.0e38f, mt1 = -3.0e38f;
        #pragma unroll
        for (int nt = 0; nt < 8; nt++) {
            float2 ma = *(const float2*)(mrow0 + kt + nt*8 + lc2);
            float2 mb = *(const float2*)(mrow1 + kt + nt*8 + lc2);
            sacc[nt][0] += ma.x; sacc[nt][1] += ma.y;
            sacc[nt][2] += mb.x; sacc[nt][3] += mb.y;
            mt0 = fmaxf(mt0, fmaxf(sacc[nt][0], sacc[nt][1]));
            mt1 = fmaxf(mt1, fmaxf(sacc[nt][2], sacc[nt][3]));
        }
        mt0 = fmaxf(mt0, __shfl_xor_sync(~0u, mt0, 1));
        mt0 = fmaxf(mt0, __shfl_xor_sync(~0u, mt0, 2));
        mt1 = fmaxf(mt1, __shfl_xor_sync(~0u, mt1, 1));
        mt1 = fmaxf(mt1, __shfl_xor_sync(~0u, mt1, 2));
        float mn0 = fmaxf(m0r, mt0), mn1 = fmaxf(m1r, mt1);
        float c0 = __expf(m0r - mn0), c1 = __expf(m1r - mn1);
        m0r = mn0; m1r = mn1;

        float s0 = 0.f, s1 = 0.f;
        #pragma unroll
        for (int nt = 0; nt < 8; nt++) {
            sacc[nt][0] = __expf(sacc[nt][0] - mn0);
            sacc[nt][1] = __expf(sacc[nt][1] - mn0);
            sacc[nt][2] = __expf(sacc[nt][2] - mn1);
            sacc[nt][3] = __expf(sacc[nt][3] - mn1);
            s0 += sacc[nt][0] + sacc[nt][1];
            s1 += sacc[nt][2] + sacc[nt][3];
        }
        s0 += __shfl_xor_sync(~0u, s0, 1); s0 += __shfl_xor_sync(~0u, s0, 2);
        s1 += __shfl_xor_sync(~0u, s1, 1); s1 += __shfl_xor_sync(~0u, s1, 2);
        l0r = l0r * c0 + s0;
        l1r = l1r * c1 + s1;

        #pragma unroll
        for (int e = 0; e < 8; e++) {
            oacc[e][0] *= c0; oacc[e][1] *= c0;
            oacc[e][2] *= c1; oacc[e][3] *= c1;
        }

        // ---- PV: P frags repacked from sacc, V frags from smem ----
        #pragma unroll
        for (int kb = 0; kb < 4; kb++) {
            uint32_t ph[4], pl[4];
            ph[0] = packf (sacc[2*kb][0],   sacc[2*kb][1]);
            ph[1] = packf (sacc[2*kb][2],   sacc[2*kb][3]);
            ph[2] = packf (sacc[2*kb+1][0], sacc[2*kb+1][1]);
            ph[3] = packf (sacc[2*kb+1][2], sacc[2*kb+1][3]);
            pl[0] = packfl(sacc[2*kb][0],   sacc[2*kb][1]);
            pl[1] = packfl(sacc[2*kb][2],   sacc[2*kb][3]);
            pl[2] = packfl(sacc[2*kb+1][0], sacc[2*kb+1][1]);
            pl[3] = packfl(sacc[2*kb+1][2], sacc[2*kb+1][3]);
            #pragma unroll
            for (int ep = 0; ep < 4; ep++) {
                uint32_t vh[4], vl[4];
                ldsm4(vh, b4addr(st + SVH, ep*16, kb*16, AST, lane));
                ldsm4(vl, b4addr(st + SVL, ep*16, kb*16, AST, lane));
                mma16816(oacc[ep*2],   ph, vh);
                mma16816(oacc[ep*2],   ph, vl);
                mma16816(oacc[ep*2],   pl, vh);
                mma16816(oacc[ep*2+1], ph, vh+2);
                mma16816(oacc[ep*2+1], ph, vl+2);
                mma16816(oacc[ep*2+1], pl, vh+2);
            }
        }
        __syncthreads();
        if (t + 2 < NT) issue(t + 2);
    }

    // ---- normalize + write O (b, n, h*64+e), split bf16 ----
    float i0 = 1.f / l0r, i1 = 1.f / l1r;
    size_t ro0 = ((size_t)b * N_ + q0 + wq0 + lr) * C_ + h * HD_;
    size_t ro1 = ro0 + (size_t)8 * C_;
    #pragma unroll
    for (int e = 0; e < 8; e++) {
        int ec = e*8 + lc2;
        float a0 = oacc[e][0]*i0, a1 = oacc[e][1]*i0;
        float a2 = oacc[e][2]*i1, a3 = oacc[e][3]*i1;
        *(uint32_t*)(g_Oh + ro0 + ec) = packf(a0, a1);
        *(uint32_t*)(g_Ol + ro0 + ec) = packfl(a0, a1);
        *(uint32_t*)(g_Oh + ro1 + ec) = packf(a2, a3);
        *(uint32_t*)(g_Ol + ro1 + ec) = packfl(a2, a3);
    }
}

// ---------------------------------------------------------------------------
extern "C" void kernel_launch(void* const* d_in, const int* in_sizes, int n_in,
                              void* d_out, int out_size)
{
    const float* x      = (const float*)d_in[0];
    const float* fc     = (const float*)d_in[1];
    const float* fs     = (const float*)d_in[2];
    const float* mask   = (const float*)d_in[3];
    const float* w_qkv  = (const float*)d_in[4];
    const float* w_proj = (const float*)d_in[5];
    const float* b_proj = (const float*)d_in[6];
    const float* q_g    = (const float*)d_in[7];
    const float* k_g    = (const float*)d_in[8];
    float* out = (float*)d_out;

    cudaFuncSetAttribute(wgemm<0>, cudaFuncAttributeMaxDynamicSharedMemorySize, DG_SMEM);
    cudaFuncSetAttribute(wgemm<1>, cudaFuncAttributeMaxDynamicSharedMemorySize, DG_SMEM);
    cudaFuncSetAttribute(attn_fa,  cudaFuncAttributeMaxDynamicSharedMemorySize, A_SMEM);

    cvt_split<0><<<B_*N_*C_/1024, 256>>>(x);
    cvt_split<1><<<3*C_*C_/1024, 256>>>(w_qkv);
    cvt_split<2><<<C_*C_/1024, 256>>>(w_proj);

    wgemm<0><<<dim3(3*C_/128, B_*N_/128), 256, DG_SMEM>>>(nullptr, nullptr);
    rmsrope<<<(B_*H_*N_)/8, 256>>>(fc, fs, q_g, k_g);
    attn_fa<<<dim3(N_/128, H_, B_), 256, A_SMEM>>>(mask);
    wgemm<1><<<dim3(C_/128, B_*N_/128), 256, DG_SMEM>>>(b_proj, out);
}